// round 1
// baseline (speedup 1.0000x reference)
#include <cuda_runtime.h>
#include <cuda_bf16.h>
#include <math.h>

// Problem constants
#define BB 32      // batch
#define SS 64      // encoder length
#define HH 512     // hidden
#define TT 32      // decode steps
#define VV 32000   // vocab

#define TILE_K 32

// ---------------- scratch (device globals; no allocation allowed) -------------
__device__ float g_h[2][BB * HH];          // ping-pong hidden state
__device__ float g_ua[BB * SS * HH];       // Ua(keys)  [2048][512]
__device__ float g_x[BB * 3 * HH];         // [emb | ctx] per batch  [32][1536]
__device__ float g_part[4 * BB * 3 * HH];  // GRU split-K partials [s][b][1536]

// ---------------- generic C[M,N] = A[M,K] @ W[N,K]^T + bias -------------------
// grid.x = N/128, grid.y = M/32, block = 256
__global__ void gemm_tn_kernel(const float* __restrict__ A, int lda,
                               const float* __restrict__ W, int ldb,
                               float* __restrict__ C, size_t ldc,
                               const float* __restrict__ bias, int K)
{
    __shared__ float sa[TILE_K][33];   // k-major [k][m], padded
    __shared__ float sb[TILE_K][132];  // k-major [k][n], padded (132 = 33*4 floats)

    const int tid = threadIdx.x;
    const int n0 = blockIdx.x * 128;
    const int m0 = blockIdx.y * 32;
    const int vq = tid & 31;   // n-quad: n = n0 + 4*vq + i
    const int bg = tid >> 5;   // m-group: m = m0 + 4*bg + j
    const int lm = tid >> 3;       // 0..31  (load row)
    const int lk = (tid & 7) * 4;  // 0..28  (load k-quad)

    float acc[4][4] = {};

    for (int k0 = 0; k0 < K; k0 += TILE_K) {
        // A tile 32x32
        {
            float4 a4 = *(const float4*)(A + (size_t)(m0 + lm) * lda + k0 + lk);
            sa[lk + 0][lm] = a4.x; sa[lk + 1][lm] = a4.y;
            sa[lk + 2][lm] = a4.z; sa[lk + 3][lm] = a4.w;
        }
        // W tile 128x32
        #pragma unroll
        for (int it = 0; it < 4; it++) {
            int n = lm + 32 * it;
            float4 b4 = *(const float4*)(W + (size_t)(n0 + n) * ldb + k0 + lk);
            sb[lk + 0][n] = b4.x; sb[lk + 1][n] = b4.y;
            sb[lk + 2][n] = b4.z; sb[lk + 3][n] = b4.w;
        }
        __syncthreads();
        #pragma unroll 8
        for (int k = 0; k < TILE_K; k++) {
            float4 bv = *(const float4*)(&sb[k][vq * 4]);  // 16B aligned: 132*k+4vq
            float a0 = sa[k][bg * 4 + 0];
            float a1 = sa[k][bg * 4 + 1];
            float a2 = sa[k][bg * 4 + 2];
            float a3 = sa[k][bg * 4 + 3];
            acc[0][0] += bv.x * a0; acc[0][1] += bv.x * a1; acc[0][2] += bv.x * a2; acc[0][3] += bv.x * a3;
            acc[1][0] += bv.y * a0; acc[1][1] += bv.y * a1; acc[1][2] += bv.y * a2; acc[1][3] += bv.y * a3;
            acc[2][0] += bv.z * a0; acc[2][1] += bv.z * a1; acc[2][2] += bv.z * a2; acc[2][3] += bv.z * a3;
            acc[3][0] += bv.w * a0; acc[3][1] += bv.w * a1; acc[3][2] += bv.w * a2; acc[3][3] += bv.w * a3;
        }
        __syncthreads();
    }

    float4 bs4 = *(const float4*)(bias + n0 + vq * 4);
    #pragma unroll
    for (int j = 0; j < 4; j++) {
        float4 o;
        o.x = acc[0][j] + bs4.x;
        o.y = acc[1][j] + bs4.y;
        o.z = acc[2][j] + bs4.z;
        o.w = acc[3][j] + bs4.w;
        *(float4*)(C + (size_t)(m0 + bg * 4 + j) * ldc + n0 + vq * 4) = o;
    }
}

// ---------------- attention + context + x assembly (one block per batch) ------
__global__ void attn_kernel(const float* __restrict__ h,
                            const float* __restrict__ Wa_w, const float* __restrict__ Wa_b,
                            const float* __restrict__ Va_w, const float* __restrict__ Va_b,
                            const float* __restrict__ ua,
                            const float* __restrict__ enc,
                            const float* __restrict__ emb,
                            const int* __restrict__ target,
                            float* __restrict__ x,
                            float* __restrict__ attn_out,
                            int t)
{
    __shared__ float sh_h[HH], sh_q[HH], sh_va[HH], sh_sc[SS], sh_ms[2];
    const int b = blockIdx.x;
    const int tid = threadIdx.x;          // 256
    const int warp = tid >> 5, lane = tid & 31;

    for (int i = tid; i < HH; i += 256) {
        sh_h[i] = h[b * HH + i];
        sh_va[i] = Va_w[i];
    }
    __syncthreads();

    // q_i = dot(h, Wa_w[i,:]) + Wa_b[i]   (warp per i, coalesced row read)
    for (int ii = 0; ii < 64; ii++) {
        int i = warp + 8 * ii;
        const float* wrow = Wa_w + (size_t)i * HH;
        float sum = 0.f;
        #pragma unroll 4
        for (int k = lane; k < HH; k += 32) sum += sh_h[k] * wrow[k];
        #pragma unroll
        for (int o = 16; o; o >>= 1) sum += __shfl_xor_sync(~0u, sum, o);
        if (lane == 0) sh_q[i] = sum + Wa_b[i];
    }
    __syncthreads();

    // scores_s = sum_h tanh(q_h + ua[b,s,h]) * Va_w[h] + Va_b
    for (int si = 0; si < 8; si++) {
        int s = warp + 8 * si;
        const float* urow = ua + (size_t)(b * SS + s) * HH;
        float sum = 0.f;
        #pragma unroll 4
        for (int k = lane; k < HH; k += 32) sum += tanhf(sh_q[k] + urow[k]) * sh_va[k];
        #pragma unroll
        for (int o = 16; o; o >>= 1) sum += __shfl_xor_sync(~0u, sum, o);
        if (lane == 0) sh_sc[s] = sum + Va_b[0];
    }
    __syncthreads();

    if (tid == 0) {
        float m = sh_sc[0];
        for (int s = 1; s < SS; s++) m = fmaxf(m, sh_sc[s]);
        float ssum = 0.f;
        for (int s = 0; s < SS; s++) ssum += expf(sh_sc[s] - m);
        sh_ms[0] = m; sh_ms[1] = ssum;
    }
    __syncthreads();
    if (tid < SS) {
        float w = expf(sh_sc[tid] - sh_ms[0]) / sh_ms[1];
        sh_sc[tid] = w;
        attn_out[((size_t)b * TT + t) * SS + tid] = w;
    }
    __syncthreads();

    // ctx_k = sum_s w_s * enc[b,s,k]   (k in [0,1024))
    for (int k = tid; k < 2 * HH; k += 256) {
        float a = 0.f;
        #pragma unroll 8
        for (int s = 0; s < SS; s++)
            a += sh_sc[s] * enc[(size_t)(b * SS + s) * (2 * HH) + k];
        x[b * 3 * HH + HH + k] = a;
    }
    // x_emb
    int tok = (t == 0) ? 0 : target[b * TT + (t - 1)];
    for (int i = tid; i < HH; i += 256)
        x[b * 3 * HH + i] = emb[(size_t)tok * HH + i];
}

// ---------------- GRU split-K partial GEMM ------------------------------------
// grid = (24 n-tiles of 64 rows, 4 k-slices), block = 128
// slices 0..2: x[b, s*512 : s*512+512] with W_ih rows; slice 3: h with W_hh
__global__ void gru_gemm_kernel(const float* __restrict__ x,   // [32][1536]
                                const float* __restrict__ h,   // [32][512]
                                const float* __restrict__ W_ih,
                                const float* __restrict__ W_hh,
                                float* __restrict__ part)      // [4][32][1536]
{
    __shared__ float sxh[TILE_K][33];
    __shared__ float sw[TILE_K][68];   // 68 = 17*4 floats, float4-aligned rows

    const int tid = threadIdx.x;       // 128
    const int s = blockIdx.y;
    const int n0 = blockIdx.x * 64;

    const float* xb; int ldx; const float* wb; int ldw;
    if (s < 3) { xb = x + s * HH; ldx = 3 * HH; wb = W_ih + s * HH; ldw = 3 * HH; }
    else       { xb = h;          ldx = HH;     wb = W_hh;          ldw = HH; }

    const int vq = tid & 15;   // n = n0 + 4*vq + i
    const int bg = tid >> 4;   // b = 4*bg + j
    const int lb = tid >> 2;        // 0..31
    const int lk = (tid & 3) * 4;   // 0..12
    const int ln = tid >> 3;        // 0..15
    const int lk8 = (tid & 7) * 4;  // 0..28

    float acc[4][4] = {};

    for (int k0 = 0; k0 < HH; k0 += TILE_K) {
        #pragma unroll
        for (int it = 0; it < 2; it++) {
            int kk = lk + 16 * it;
            float4 a4 = *(const float4*)(xb + (size_t)lb * ldx + k0 + kk);
            sxh[kk + 0][lb] = a4.x; sxh[kk + 1][lb] = a4.y;
            sxh[kk + 2][lb] = a4.z; sxh[kk + 3][lb] = a4.w;
        }
        #pragma unroll
        for (int it = 0; it < 4; it++) {
            int n = ln + 16 * it;
            float4 w4 = *(const float4*)(wb + (size_t)(n0 + n) * ldw + k0 + lk8);
            sw[lk8 + 0][n] = w4.x; sw[lk8 + 1][n] = w4.y;
            sw[lk8 + 2][n] = w4.z; sw[lk8 + 3][n] = w4.w;
        }
        __syncthreads();
        #pragma unroll 8
        for (int k = 0; k < TILE_K; k++) {
            float4 wv = *(const float4*)(&sw[k][vq * 4]);  // aligned: 68k+4vq
            float a0 = sxh[k][bg * 4 + 0];
            float a1 = sxh[k][bg * 4 + 1];
            float a2 = sxh[k][bg * 4 + 2];
            float a3 = sxh[k][bg * 4 + 3];
            acc[0][0] += wv.x * a0; acc[0][1] += wv.x * a1; acc[0][2] += wv.x * a2; acc[0][3] += wv.x * a3;
            acc[1][0] += wv.y * a0; acc[1][1] += wv.y * a1; acc[1][2] += wv.y * a2; acc[1][3] += wv.y * a3;
            acc[2][0] += wv.z * a0; acc[2][1] += wv.z * a1; acc[2][2] += wv.z * a2; acc[2][3] += wv.z * a3;
            acc[3][0] += wv.w * a0; acc[3][1] += wv.w * a1; acc[3][2] += wv.w * a2; acc[3][3] += wv.w * a3;
        }
        __syncthreads();
    }

    #pragma unroll
    for (int j = 0; j < 4; j++) {
        int b = bg * 4 + j;
        float4 o;
        o.x = acc[0][j]; o.y = acc[1][j]; o.z = acc[2][j]; o.w = acc[3][j];
        *(float4*)(part + ((size_t)s * BB + b) * (3 * HH) + n0 + vq * 4) = o;
    }
}

// ---------------- GRU gate fusion ---------------------------------------------
__global__ void gru_gates_kernel(const float* __restrict__ part,
                                 const float* __restrict__ b_ih,
                                 const float* __restrict__ b_hh,
                                 const float* __restrict__ h_old,
                                 float* __restrict__ h_new)
{
    const int b = blockIdx.x;
    const int j = threadIdx.x;  // 512
    const float* p0 = part + ((size_t)0 * BB + b) * (3 * HH);
    const float* p1 = part + ((size_t)1 * BB + b) * (3 * HH);
    const float* p2 = part + ((size_t)2 * BB + b) * (3 * HH);
    const float* p3 = part + ((size_t)3 * BB + b) * (3 * HH);

    float gx_r = p0[j] + p1[j] + p2[j] + b_ih[j];
    float gh_r = p3[j] + b_hh[j];
    float gx_z = p0[j + HH] + p1[j + HH] + p2[j + HH] + b_ih[j + HH];
    float gh_z = p3[j + HH] + b_hh[j + HH];
    float gx_n = p0[j + 2 * HH] + p1[j + 2 * HH] + p2[j + 2 * HH] + b_ih[j + 2 * HH];
    float gh_n = p3[j + 2 * HH] + b_hh[j + 2 * HH];

    float r = 1.f / (1.f + expf(-(gx_r + gh_r)));
    float z = 1.f / (1.f + expf(-(gx_z + gh_z)));
    float n = tanhf(gx_n + r * gh_n);
    float hv = h_old[b * HH + j];
    h_new[b * HH + j] = (1.f - z) * n + z * hv;
}

// ---------------- in-place log_softmax over V (block per batch row) -----------
__global__ void lsm_kernel(float* __restrict__ out, int t)
{
    const int b = blockIdx.x;
    float* row = out + ((size_t)b * TT + t) * VV;
    __shared__ float red[8];
    __shared__ float sh_m, sh_s;
    const int tid = threadIdx.x;  // 256
    const int warp = tid >> 5, lane = tid & 31;

    float m = -1e30f;
    for (int i = tid; i < VV; i += 256) m = fmaxf(m, row[i]);
    #pragma unroll
    for (int o = 16; o; o >>= 1) m = fmaxf(m, __shfl_xor_sync(~0u, m, o));
    if (lane == 0) red[warp] = m;
    __syncthreads();
    if (tid == 0) {
        float mm = red[0];
        for (int w = 1; w < 8; w++) mm = fmaxf(mm, red[w]);
        sh_m = mm;
    }
    __syncthreads();
    float mb = sh_m;

    float s = 0.f;
    for (int i = tid; i < VV; i += 256) s += expf(row[i] - mb);
    #pragma unroll
    for (int o = 16; o; o >>= 1) s += __shfl_xor_sync(~0u, s, o);
    if (lane == 0) red[warp] = s;
    __syncthreads();
    if (tid == 0) {
        float ss = 0.f;
        for (int w = 0; w < 8; w++) ss += red[w];
        sh_s = ss;
    }
    __syncthreads();
    float ls = mb + logf(sh_s);

    for (int i = tid; i < VV; i += 256) row[i] = row[i] - ls;
}

// ---------------- final hidden copy -------------------------------------------
__global__ void copy_kernel(const float* __restrict__ src, float* __restrict__ dst, int n)
{
    int i = blockIdx.x * blockDim.x + threadIdx.x;
    if (i < n) dst[i] = src[i];
}

// ---------------- host launcher ------------------------------------------------
extern "C" void kernel_launch(void* const* d_in, const int* in_sizes, int n_in,
                              void* d_out, int out_size)
{
    const float* enc   = (const float*)d_in[0];   // [32,64,1024]
    const float* ehid  = (const float*)d_in[1];   // [1,32,1024]
    const int*   tgt   = (const int*)  d_in[2];   // [32,32]
    const float* emb   = (const float*)d_in[3];   // [32000,512]
    const float* Wa_w  = (const float*)d_in[4];   // [512,512]
    const float* Wa_b  = (const float*)d_in[5];
    const float* Ua_w  = (const float*)d_in[6];   // [512,1024]
    const float* Ua_b  = (const float*)d_in[7];
    const float* Va_w  = (const float*)d_in[8];   // [1,512]
    const float* Va_b  = (const float*)d_in[9];
    const float* W_ih  = (const float*)d_in[10];  // [1536,1536]
    const float* b_ih  = (const float*)d_in[11];
    const float* W_hh  = (const float*)d_in[12];  // [1536,512]
    const float* b_hh  = (const float*)d_in[13];
    const float* Wh    = (const float*)d_in[14];  // [512,1024]
    const float* bh    = (const float*)d_in[15];
    const float* out_w = (const float*)d_in[16];  // [32000,512]
    const float* out_b = (const float*)d_in[17];

    float* outp = (float*)d_out;
    float* logp = outp;                                   // [32][32][32000]
    float* hfin = outp + (size_t)BB * TT * VV;            // [1][32][512]
    float* attn = hfin + (size_t)BB * HH;                 // [32][32][64]

    float *g_h_p, *g_ua_p, *g_x_p, *g_part_p;
    cudaGetSymbolAddress((void**)&g_h_p, g_h);
    cudaGetSymbolAddress((void**)&g_ua_p, g_ua);
    cudaGetSymbolAddress((void**)&g_x_p, g_x);
    cudaGetSymbolAddress((void**)&g_part_p, g_part);

    // h0 = encoder_hidden @ Wh^T + bh : [32,512]
    gemm_tn_kernel<<<dim3(HH / 128, 1), 256>>>(ehid, 2 * HH, Wh, 2 * HH,
                                               g_h_p, HH, bh, 2 * HH);
    // ua_keys = enc @ Ua_w^T + Ua_b : [2048,512]
    gemm_tn_kernel<<<dim3(HH / 128, (BB * SS) / 32), 256>>>(enc, 2 * HH, Ua_w, 2 * HH,
                                                            g_ua_p, HH, Ua_b, 2 * HH);

    for (int t = 0; t < TT; t++) {
        float* cur = g_h_p + (size_t)(t & 1) * BB * HH;
        float* nxt = g_h_p + (size_t)((t + 1) & 1) * BB * HH;

        attn_kernel<<<BB, 256>>>(cur, Wa_w, Wa_b, Va_w, Va_b,
                                 g_ua_p, enc, emb, tgt, g_x_p, attn, t);
        gru_gemm_kernel<<<dim3(24, 4), 128>>>(g_x_p, cur, W_ih, W_hh, g_part_p);
        gru_gates_kernel<<<BB, HH>>>(g_part_p, b_ih, b_hh, cur, nxt);
        // logits -> d_out rows (b*T + t), ldc = T*V
        gemm_tn_kernel<<<dim3(VV / 128, 1), 256>>>(nxt, HH, out_w, HH,
                                                   logp + (size_t)t * VV,
                                                   (size_t)TT * VV, out_b, HH);
        lsm_kernel<<<BB, 256>>>(logp, t);
    }
    // final hidden is in buffer 0 after t=31 writes (t odd -> nxt = buf 0)
    copy_kernel<<<(BB * HH + 1023) / 1024, 1024>>>(g_h_p, hfin, BB * HH);
}

// round 2
// speedup vs baseline: 1.0015x; 1.0015x over previous
#include <cuda_runtime.h>
#include <cuda_bf16.h>
#include <math.h>

// Problem constants
#define BB 32      // batch
#define SS 64      // encoder length
#define HH 512     // hidden
#define TT 32      // decode steps
#define VV 32000   // vocab

#define TILE_K 32

// ---------------- scratch (device globals; no allocation allowed) -------------
__device__ float g_h[2][BB * HH];          // ping-pong hidden state
__device__ float g_ua[BB * SS * HH];       // Ua(keys)  [2048][512]
__device__ float g_x[BB * 3 * HH];         // [emb | ctx] per batch  [32][1536]
__device__ float g_part[4 * BB * 3 * HH];  // GRU split-K partials [s][b][1536]

// ---------------- generic C[M,N] = A[M,K] @ W[N,K]^T + bias -------------------
// grid.x = N/128, grid.y = M/32, block = 256
__global__ void gemm_tn_kernel(const float* __restrict__ A, int lda,
                               const float* __restrict__ W, int ldb,
                               float* __restrict__ C, size_t ldc,
                               const float* __restrict__ bias, int K)
{
    __shared__ float sa[TILE_K][33];   // k-major [k][m], padded
    __shared__ float sb[TILE_K][132];  // k-major [k][n], padded (132 = 33*4 floats)

    const int tid = threadIdx.x;
    const int n0 = blockIdx.x * 128;
    const int m0 = blockIdx.y * 32;
    const int vq = tid & 31;   // n-quad: n = n0 + 4*vq + i
    const int bg = tid >> 5;   // m-group: m = m0 + 4*bg + j
    const int lm = tid >> 3;       // 0..31  (load row)
    const int lk = (tid & 7) * 4;  // 0..28  (load k-quad)

    float acc[4][4] = {};

    for (int k0 = 0; k0 < K; k0 += TILE_K) {
        // A tile 32x32
        {
            float4 a4 = *(const float4*)(A + (size_t)(m0 + lm) * lda + k0 + lk);
            sa[lk + 0][lm] = a4.x; sa[lk + 1][lm] = a4.y;
            sa[lk + 2][lm] = a4.z; sa[lk + 3][lm] = a4.w;
        }
        // W tile 128x32
        #pragma unroll
        for (int it = 0; it < 4; it++) {
            int n = lm + 32 * it;
            float4 b4 = *(const float4*)(W + (size_t)(n0 + n) * ldb + k0 + lk);
            sb[lk + 0][n] = b4.x; sb[lk + 1][n] = b4.y;
            sb[lk + 2][n] = b4.z; sb[lk + 3][n] = b4.w;
        }
        __syncthreads();
        #pragma unroll 8
        for (int k = 0; k < TILE_K; k++) {
            float4 bv = *(const float4*)(&sb[k][vq * 4]);  // 16B aligned: 132*k+4vq
            float a0 = sa[k][bg * 4 + 0];
            float a1 = sa[k][bg * 4 + 1];
            float a2 = sa[k][bg * 4 + 2];
            float a3 = sa[k][bg * 4 + 3];
            acc[0][0] += bv.x * a0; acc[0][1] += bv.x * a1; acc[0][2] += bv.x * a2; acc[0][3] += bv.x * a3;
            acc[1][0] += bv.y * a0; acc[1][1] += bv.y * a1; acc[1][2] += bv.y * a2; acc[1][3] += bv.y * a3;
            acc[2][0] += bv.z * a0; acc[2][1] += bv.z * a1; acc[2][2] += bv.z * a2; acc[2][3] += bv.z * a3;
            acc[3][0] += bv.w * a0; acc[3][1] += bv.w * a1; acc[3][2] += bv.w * a2; acc[3][3] += bv.w * a3;
        }
        __syncthreads();
    }

    float4 bs4 = *(const float4*)(bias + n0 + vq * 4);
    #pragma unroll
    for (int j = 0; j < 4; j++) {
        float4 o;
        o.x = acc[0][j] + bs4.x;
        o.y = acc[1][j] + bs4.y;
        o.z = acc[2][j] + bs4.z;
        o.w = acc[3][j] + bs4.w;
        *(float4*)(C + (size_t)(m0 + bg * 4 + j) * ldc + n0 + vq * 4) = o;
    }
}

// ---------------- attention + context + x assembly (one block per batch) ------
__global__ void attn_kernel(const float* __restrict__ h,
                            const float* __restrict__ Wa_w, const float* __restrict__ Wa_b,
                            const float* __restrict__ Va_w, const float* __restrict__ Va_b,
                            const float* __restrict__ ua,
                            const float* __restrict__ enc,
                            const float* __restrict__ emb,
                            const int* __restrict__ target,
                            float* __restrict__ x,
                            float* __restrict__ attn_out,
                            int t)
{
    __shared__ float sh_h[HH], sh_q[HH], sh_va[HH], sh_sc[SS], sh_ms[2];
    const int b = blockIdx.x;
    const int tid = threadIdx.x;          // 256
    const int warp = tid >> 5, lane = tid & 31;

    for (int i = tid; i < HH; i += 256) {
        sh_h[i] = h[b * HH + i];
        sh_va[i] = Va_w[i];
    }
    __syncthreads();

    // q_i = dot(h, Wa_w[i,:]) + Wa_b[i]   (warp per i, coalesced row read)
    for (int ii = 0; ii < 64; ii++) {
        int i = warp + 8 * ii;
        const float* wrow = Wa_w + (size_t)i * HH;
        float sum = 0.f;
        #pragma unroll 4
        for (int k = lane; k < HH; k += 32) sum += sh_h[k] * wrow[k];
        #pragma unroll
        for (int o = 16; o; o >>= 1) sum += __shfl_xor_sync(~0u, sum, o);
        if (lane == 0) sh_q[i] = sum + Wa_b[i];
    }
    __syncthreads();

    // scores_s = sum_h tanh(q_h + ua[b,s,h]) * Va_w[h] + Va_b
    for (int si = 0; si < 8; si++) {
        int s = warp + 8 * si;
        const float* urow = ua + (size_t)(b * SS + s) * HH;
        float sum = 0.f;
        #pragma unroll 4
        for (int k = lane; k < HH; k += 32) sum += tanhf(sh_q[k] + urow[k]) * sh_va[k];
        #pragma unroll
        for (int o = 16; o; o >>= 1) sum += __shfl_xor_sync(~0u, sum, o);
        if (lane == 0) sh_sc[s] = sum + Va_b[0];
    }
    __syncthreads();

    if (tid == 0) {
        float m = sh_sc[0];
        for (int s = 1; s < SS; s++) m = fmaxf(m, sh_sc[s]);
        float ssum = 0.f;
        for (int s = 0; s < SS; s++) ssum += expf(sh_sc[s] - m);
        sh_ms[0] = m; sh_ms[1] = ssum;
    }
    __syncthreads();
    if (tid < SS) {
        float w = expf(sh_sc[tid] - sh_ms[0]) / sh_ms[1];
        sh_sc[tid] = w;
        attn_out[((size_t)b * TT + t) * SS + tid] = w;
    }
    __syncthreads();

    // ctx_k = sum_s w_s * enc[b,s,k]   (k in [0,1024))
    for (int k = tid; k < 2 * HH; k += 256) {
        float a = 0.f;
        #pragma unroll 8
        for (int s = 0; s < SS; s++)
            a += sh_sc[s] * enc[(size_t)(b * SS + s) * (2 * HH) + k];
        x[b * 3 * HH + HH + k] = a;
    }
    // x_emb
    int tok = (t == 0) ? 0 : target[b * TT + (t - 1)];
    for (int i = tid; i < HH; i += 256)
        x[b * 3 * HH + i] = emb[(size_t)tok * HH + i];
}

// ---------------- GRU split-K partial GEMM ------------------------------------
// grid = (24 n-tiles of 64 rows, 4 k-slices), block = 128
// slices 0..2: x[b, s*512 : s*512+512] with W_ih rows; slice 3: h with W_hh
__global__ void gru_gemm_kernel(const float* __restrict__ x,   // [32][1536]
                                const float* __restrict__ h,   // [32][512]
                                const float* __restrict__ W_ih,
                                const float* __restrict__ W_hh,
                                float* __restrict__ part)      // [4][32][1536]
{
    __shared__ float sxh[TILE_K][33];
    __shared__ float sw[TILE_K][68];   // 68 = 17*4 floats, float4-aligned rows

    const int tid = threadIdx.x;       // 128
    const int s = blockIdx.y;
    const int n0 = blockIdx.x * 64;

    const float* xb; int ldx; const float* wb; int ldw;
    if (s < 3) { xb = x + s * HH; ldx = 3 * HH; wb = W_ih + s * HH; ldw = 3 * HH; }
    else       { xb = h;          ldx = HH;     wb = W_hh;          ldw = HH; }

    const int vq = tid & 15;   // n = n0 + 4*vq + i
    const int bg = tid >> 4;   // b = 4*bg + j
    const int lb = tid >> 2;        // 0..31
    const int lk = (tid & 3) * 4;   // 0..12
    const int ln = tid >> 3;        // 0..15
    const int lk8 = (tid & 7) * 4;  // 0..28

    float acc[4][4] = {};

    for (int k0 = 0; k0 < HH; k0 += TILE_K) {
        #pragma unroll
        for (int it = 0; it < 2; it++) {
            int kk = lk + 16 * it;
            float4 a4 = *(const float4*)(xb + (size_t)lb * ldx + k0 + kk);
            sxh[kk + 0][lb] = a4.x; sxh[kk + 1][lb] = a4.y;
            sxh[kk + 2][lb] = a4.z; sxh[kk + 3][lb] = a4.w;
        }
        #pragma unroll
        for (int it = 0; it < 4; it++) {
            int n = ln + 16 * it;
            float4 w4 = *(const float4*)(wb + (size_t)(n0 + n) * ldw + k0 + lk8);
            sw[lk8 + 0][n] = w4.x; sw[lk8 + 1][n] = w4.y;
            sw[lk8 + 2][n] = w4.z; sw[lk8 + 3][n] = w4.w;
        }
        __syncthreads();
        #pragma unroll 8
        for (int k = 0; k < TILE_K; k++) {
            float4 wv = *(const float4*)(&sw[k][vq * 4]);  // aligned: 68k+4vq
            float a0 = sxh[k][bg * 4 + 0];
            float a1 = sxh[k][bg * 4 + 1];
            float a2 = sxh[k][bg * 4 + 2];
            float a3 = sxh[k][bg * 4 + 3];
            acc[0][0] += wv.x * a0; acc[0][1] += wv.x * a1; acc[0][2] += wv.x * a2; acc[0][3] += wv.x * a3;
            acc[1][0] += wv.y * a0; acc[1][1] += wv.y * a1; acc[1][2] += wv.y * a2; acc[1][3] += wv.y * a3;
            acc[2][0] += wv.z * a0; acc[2][1] += wv.z * a1; acc[2][2] += wv.z * a2; acc[2][3] += wv.z * a3;
            acc[3][0] += wv.w * a0; acc[3][1] += wv.w * a1; acc[3][2] += wv.w * a2; acc[3][3] += wv.w * a3;
        }
        __syncthreads();
    }

    #pragma unroll
    for (int j = 0; j < 4; j++) {
        int b = bg * 4 + j;
        float4 o;
        o.x = acc[0][j]; o.y = acc[1][j]; o.z = acc[2][j]; o.w = acc[3][j];
        *(float4*)(part + ((size_t)s * BB + b) * (3 * HH) + n0 + vq * 4) = o;
    }
}

// ---------------- GRU gate fusion ---------------------------------------------
__global__ void gru_gates_kernel(const float* __restrict__ part,
                                 const float* __restrict__ b_ih,
                                 const float* __restrict__ b_hh,
                                 const float* __restrict__ h_old,
                                 float* __restrict__ h_new)
{
    const int b = blockIdx.x;
    const int j = threadIdx.x;  // 512
    const float* p0 = part + ((size_t)0 * BB + b) * (3 * HH);
    const float* p1 = part + ((size_t)1 * BB + b) * (3 * HH);
    const float* p2 = part + ((size_t)2 * BB + b) * (3 * HH);
    const float* p3 = part + ((size_t)3 * BB + b) * (3 * HH);

    float gx_r = p0[j] + p1[j] + p2[j] + b_ih[j];
    float gh_r = p3[j] + b_hh[j];
    float gx_z = p0[j + HH] + p1[j + HH] + p2[j + HH] + b_ih[j + HH];
    float gh_z = p3[j + HH] + b_hh[j + HH];
    float gx_n = p0[j + 2 * HH] + p1[j + 2 * HH] + p2[j + 2 * HH] + b_ih[j + 2 * HH];
    float gh_n = p3[j + 2 * HH] + b_hh[j + 2 * HH];

    float r = 1.f / (1.f + expf(-(gx_r + gh_r)));
    float z = 1.f / (1.f + expf(-(gx_z + gh_z)));
    float n = tanhf(gx_n + r * gh_n);
    float hv = h_old[b * HH + j];
    h_new[b * HH + j] = (1.f - z) * n + z * hv;
}

// ---------------- in-place log_softmax over V (block per batch row) -----------
__global__ void lsm_kernel(float* __restrict__ out, int t)
{
    const int b = blockIdx.x;
    float* row = out + ((size_t)b * TT + t) * VV;
    __shared__ float red[8];
    __shared__ float sh_m, sh_s;
    const int tid = threadIdx.x;  // 256
    const int warp = tid >> 5, lane = tid & 31;

    float m = -1e30f;
    for (int i = tid; i < VV; i += 256) m = fmaxf(m, row[i]);
    #pragma unroll
    for (int o = 16; o; o >>= 1) m = fmaxf(m, __shfl_xor_sync(~0u, m, o));
    if (lane == 0) red[warp] = m;
    __syncthreads();
    if (tid == 0) {
        float mm = red[0];
        for (int w = 1; w < 8; w++) mm = fmaxf(mm, red[w]);
        sh_m = mm;
    }
    __syncthreads();
    float mb = sh_m;

    float s = 0.f;
    for (int i = tid; i < VV; i += 256) s += expf(row[i] - mb);
    #pragma unroll
    for (int o = 16; o; o >>= 1) s += __shfl_xor_sync(~0u, s, o);
    if (lane == 0) red[warp] = s;
    __syncthreads();
    if (tid == 0) {
        float ss = 0.f;
        for (int w = 0; w < 8; w++) ss += red[w];
        sh_s = ss;
    }
    __syncthreads();
    float ls = mb + logf(sh_s);

    for (int i = tid; i < VV; i += 256) row[i] = row[i] - ls;
}

// ---------------- final hidden copy -------------------------------------------
__global__ void copy_kernel(const float* __restrict__ src, float* __restrict__ dst, int n)
{
    int i = blockIdx.x * blockDim.x + threadIdx.x;
    if (i < n) dst[i] = src[i];
}

// ---------------- host launcher ------------------------------------------------
extern "C" void kernel_launch(void* const* d_in, const int* in_sizes, int n_in,
                              void* d_out, int out_size)
{
    const float* enc   = (const float*)d_in[0];   // [32,64,1024]
    const float* ehid  = (const float*)d_in[1];   // [1,32,1024]
    const int*   tgt   = (const int*)  d_in[2];   // [32,32]
    const float* emb   = (const float*)d_in[3];   // [32000,512]
    const float* Wa_w  = (const float*)d_in[4];   // [512,512]
    const float* Wa_b  = (const float*)d_in[5];
    const float* Ua_w  = (const float*)d_in[6];   // [512,1024]
    const float* Ua_b  = (const float*)d_in[7];
    const float* Va_w  = (const float*)d_in[8];   // [1,512]
    const float* Va_b  = (const float*)d_in[9];
    const float* W_ih  = (const float*)d_in[10];  // [1536,1536]
    const float* b_ih  = (const float*)d_in[11];
    const float* W_hh  = (const float*)d_in[12];  // [1536,512]
    const float* b_hh  = (const float*)d_in[13];
    const float* Wh    = (const float*)d_in[14];  // [512,1024]
    const float* bh    = (const float*)d_in[15];
    const float* out_w = (const float*)d_in[16];  // [32000,512]
    const float* out_b = (const float*)d_in[17];

    float* outp = (float*)d_out;
    float* logp = outp;                                   // [32][32][32000]
    float* hfin = outp + (size_t)BB * TT * VV;            // [1][32][512]
    float* attn = hfin + (size_t)BB * HH;                 // [32][32][64]

    float *g_h_p, *g_ua_p, *g_x_p, *g_part_p;
    cudaGetSymbolAddress((void**)&g_h_p, g_h);
    cudaGetSymbolAddress((void**)&g_ua_p, g_ua);
    cudaGetSymbolAddress((void**)&g_x_p, g_x);
    cudaGetSymbolAddress((void**)&g_part_p, g_part);

    // h0 = encoder_hidden @ Wh^T + bh : [32,512]
    gemm_tn_kernel<<<dim3(HH / 128, 1), 256>>>(ehid, 2 * HH, Wh, 2 * HH,
                                               g_h_p, HH, bh, 2 * HH);
    // ua_keys = enc @ Ua_w^T + Ua_b : [2048,512]
    gemm_tn_kernel<<<dim3(HH / 128, (BB * SS) / 32), 256>>>(enc, 2 * HH, Ua_w, 2 * HH,
                                                            g_ua_p, HH, Ua_b, 2 * HH);

    for (int t = 0; t < TT; t++) {
        float* cur = g_h_p + (size_t)(t & 1) * BB * HH;
        float* nxt = g_h_p + (size_t)((t + 1) & 1) * BB * HH;

        attn_kernel<<<BB, 256>>>(cur, Wa_w, Wa_b, Va_w, Va_b,
                                 g_ua_p, enc, emb, tgt, g_x_p, attn, t);
        gru_gemm_kernel<<<dim3(24, 4), 128>>>(g_x_p, cur, W_ih, W_hh, g_part_p);
        gru_gates_kernel<<<BB, HH>>>(g_part_p, b_ih, b_hh, cur, nxt);
        // logits -> d_out rows (b*T + t), ldc = T*V
        gemm_tn_kernel<<<dim3(VV / 128, 1), 256>>>(nxt, HH, out_w, HH,
                                                   logp + (size_t)t * VV,
                                                   (size_t)TT * VV, out_b, HH);
        lsm_kernel<<<BB, 256>>>(logp, t);
    }
    // final hidden is in buffer 0 after t=31 writes (t odd -> nxt = buf 0)
    copy_kernel<<<(BB * HH + 1023) / 1024, 1024>>>(g_h_p, hfin, BB * HH);
}

// round 3
// speedup vs baseline: 2.6229x; 2.6190x over previous
#include <cuda_runtime.h>
#include <math.h>

#define BB 32
#define SS 64
#define HH 512
#define TT 32
#define VV 32000
#define TILE_K 32

// ---------------- device scratch ----------------------------------------------
__device__ float g_Hall[(TT + 1) * BB * HH];   // h slots 0..32
__device__ float g_eu[BB * SS * HH];           // exp(2*ua_keys)
__device__ float g_gxe[TT * BB * 3 * HH];      // emb@W_ih_embT + b_ih
__device__ float g_qp[4 * BB * HH];            // q split-K partials
__device__ float g_sc[BB * SS];                // scores
__device__ float g_ctx[BB * 2 * HH];           // context
__device__ float g_part[3 * BB * 3 * HH];      // GRU split-K partials
__device__ float g_psum[BB * TT * 256];        // exp row partials
__device__ int   g_tok[TT * BB];               // tokens [t][b]

typedef unsigned long long ull;
__device__ __forceinline__ void ffma2(ull& d, ull a, ull b) {
    asm("fma.rn.f32x2 %0, %1, %2, %0;" : "+l"(d) : "l"(a), "l"(b));
}
__device__ __forceinline__ float2 unpack2(ull v) {
    float2 r; asm("mov.b64 {%0, %1}, %2;" : "=f"(r.x), "=f"(r.y) : "l"(v)); return r;
}
__device__ __forceinline__ float rcpf(float x) {
    float r; asm("rcp.approx.f32 %0, %1;" : "=f"(r) : "f"(x)); return r;
}
__device__ __forceinline__ float sig_f(float x) {
    x = fminf(fmaxf(x, -30.f), 30.f);
    return rcpf(1.f + __expf(-x));
}
__device__ __forceinline__ float tanh_f(float x) {
    x = fminf(fmaxf(x, -15.f), 15.f);
    float e = __expf(2.f * x);
    return 1.f - 2.f * rcpf(e + 1.f);
}

// ---------------- tokens -------------------------------------------------------
__global__ void tok_kernel(const int* __restrict__ tgt) {
    int i = blockIdx.x * 256 + threadIdx.x;
    if (i < TT * BB) {
        int t = i >> 5, b = i & 31;
        g_tok[i] = (t == 0) ? 0 : tgt[b * TT + t - 1];
    }
}

// ---------------- big 128x128 GEMM, f32x2 math ---------------------------------
// C[M,N] = A[M,K]@W[N,K]^T + bias. mode 0: logits (permuted rows + exp psum),
// mode 1: plain, mode 2: store exp(2v). tokens!=null -> gather A rows.
__global__ __launch_bounds__(256, 2)
void big128_kernel(const float* __restrict__ A, int lda,
                   const int* __restrict__ tokens,
                   const float* __restrict__ W, int ldw,
                   const float* __restrict__ bias, int K,
                   float* __restrict__ C, int ldc, int mode,
                   float* __restrict__ psum)
{
    __shared__ __align__(16) float sA[16][132];
    __shared__ __align__(16) float2 sBd[16][128];
    const int tid = threadIdx.x;
    const int n0 = blockIdx.x * 128;
    const int m0 = blockIdx.y * 128;
    const int tx4 = (tid & 15) * 4;
    const int ty4 = (tid >> 4) * 4;

    ull acc[4][8];
    #pragma unroll
    for (int i = 0; i < 4; i++)
        #pragma unroll
        for (int j = 0; j < 8; j++) acc[i][j] = 0ull;

    for (int k0 = 0; k0 < K; k0 += 16) {
        #pragma unroll
        for (int q = 0; q < 2; q++) {
            int idx = tid + 256 * q;
            int row = idx >> 2, kq = (idx & 3) * 4;
            long ar = tokens ? (long)tokens[m0 + row] : (long)(m0 + row);
            float4 av = *(const float4*)(A + ar * lda + k0 + kq);
            sA[kq + 0][row] = av.x; sA[kq + 1][row] = av.y;
            sA[kq + 2][row] = av.z; sA[kq + 3][row] = av.w;
            float4 wv = *(const float4*)(W + (size_t)(n0 + row) * ldw + k0 + kq);
            sBd[kq + 0][row] = make_float2(wv.x, wv.x);
            sBd[kq + 1][row] = make_float2(wv.y, wv.y);
            sBd[kq + 2][row] = make_float2(wv.z, wv.z);
            sBd[kq + 3][row] = make_float2(wv.w, wv.w);
        }
        __syncthreads();
        #pragma unroll
        for (int k = 0; k < 16; k++) {
            ulonglong2 a0 = *(const ulonglong2*)&sA[k][ty4];
            ulonglong2 a1 = *(const ulonglong2*)&sA[k][64 + ty4];
            ulonglong2 b0 = *(const ulonglong2*)&sBd[k][tx4];
            ulonglong2 b1 = *(const ulonglong2*)&sBd[k][tx4 + 2];
            ulonglong2 b2 = *(const ulonglong2*)&sBd[k][64 + tx4];
            ulonglong2 b3 = *(const ulonglong2*)&sBd[k][64 + tx4 + 2];
            ull ap[4] = {a0.x, a0.y, a1.x, a1.y};
            ull bd[8] = {b0.x, b0.y, b1.x, b1.y, b2.x, b2.y, b3.x, b3.y};
            #pragma unroll
            for (int mp = 0; mp < 4; mp++)
                #pragma unroll
                for (int n = 0; n < 8; n++)
                    ffma2(acc[mp][n], ap[mp], bd[n]);
        }
        __syncthreads();
    }

    float4 bs0 = *(const float4*)&bias[n0 + tx4];
    float4 bs1 = *(const float4*)&bias[n0 + 64 + tx4];
    #pragma unroll
    for (int mp = 0; mp < 4; mp++) {
        #pragma unroll
        for (int half = 0; half < 2; half++) {
            int gm = m0 + (mp >> 1) * 64 + ty4 + (mp & 1) * 2 + half;
            float v[8];
            #pragma unroll
            for (int n = 0; n < 8; n++) {
                float2 p = unpack2(acc[mp][n]);
                v[n] = half ? p.y : p.x;
            }
            v[0] += bs0.x; v[1] += bs0.y; v[2] += bs0.z; v[3] += bs0.w;
            v[4] += bs1.x; v[5] += bs1.y; v[6] += bs1.z; v[7] += bs1.w;
            if (mode == 2) {
                #pragma unroll
                for (int n = 0; n < 8; n++) v[n] = __expf(2.f * v[n]);
            }
            float* cp;
            if (mode == 0) {
                int tq = gm >> 5, bq = gm & 31;
                cp = C + (size_t)(bq * TT + tq) * VV + n0;
            } else {
                cp = C + (size_t)gm * ldc + n0;
            }
            *(float4*)(cp + tx4)      = make_float4(v[0], v[1], v[2], v[3]);
            *(float4*)(cp + 64 + tx4) = make_float4(v[4], v[5], v[6], v[7]);
            if (mode == 0) {
                float es = 0.f;
                #pragma unroll
                for (int n = 0; n < 8; n++) es += __expf(v[n]);
                #pragma unroll
                for (int o = 8; o; o >>= 1)
                    es += __shfl_down_sync(0xffffffffu, es, o, 16);
                if ((tid & 15) == 0) {
                    int tq = gm >> 5, bq = gm & 31;
                    psum[(size_t)(bq * TT + tq) * 256 + blockIdx.x] = es;
                }
            }
        }
    }
}

// ---------------- small gemm (h0 only): C[32,N]=A@W^T+bias --------------------
__global__ void gemm_tn_kernel(const float* __restrict__ A, int lda,
                               const float* __restrict__ W, int ldb,
                               float* __restrict__ C, int ldc,
                               const float* __restrict__ bias, int K)
{
    __shared__ float sa[TILE_K][33];
    __shared__ float sb[TILE_K][132];
    const int tid = threadIdx.x;
    const int n0 = blockIdx.x * 128;
    const int vq = tid & 31, bg = tid >> 5;
    const int lm = tid >> 3, lk = (tid & 7) * 4;
    float acc[4][4] = {};
    for (int k0 = 0; k0 < K; k0 += TILE_K) {
        float4 a4 = *(const float4*)(A + (size_t)lm * lda + k0 + lk);
        sa[lk + 0][lm] = a4.x; sa[lk + 1][lm] = a4.y;
        sa[lk + 2][lm] = a4.z; sa[lk + 3][lm] = a4.w;
        #pragma unroll
        for (int it = 0; it < 4; it++) {
            int n = lm + 32 * it;
            float4 b4 = *(const float4*)(W + (size_t)(n0 + n) * ldb + k0 + lk);
            sb[lk + 0][n] = b4.x; sb[lk + 1][n] = b4.y;
            sb[lk + 2][n] = b4.z; sb[lk + 3][n] = b4.w;
        }
        __syncthreads();
        #pragma unroll 8
        for (int k = 0; k < TILE_K; k++) {
            float4 bv = *(const float4*)(&sb[k][vq * 4]);
            float a0 = sa[k][bg * 4 + 0], a1 = sa[k][bg * 4 + 1];
            float a2 = sa[k][bg * 4 + 2], a3 = sa[k][bg * 4 + 3];
            acc[0][0] += bv.x * a0; acc[0][1] += bv.x * a1; acc[0][2] += bv.x * a2; acc[0][3] += bv.x * a3;
            acc[1][0] += bv.y * a0; acc[1][1] += bv.y * a1; acc[1][2] += bv.y * a2; acc[1][3] += bv.y * a3;
            acc[2][0] += bv.z * a0; acc[2][1] += bv.z * a1; acc[2][2] += bv.z * a2; acc[2][3] += bv.z * a3;
            acc[3][0] += bv.w * a0; acc[3][1] += bv.w * a1; acc[3][2] += bv.w * a2; acc[3][3] += bv.w * a3;
        }
        __syncthreads();
    }
    float4 bs4 = *(const float4*)(bias + n0 + vq * 4);
    #pragma unroll
    for (int j = 0; j < 4; j++) {
        float4 o;
        o.x = acc[0][j] + bs4.x; o.y = acc[1][j] + bs4.y;
        o.z = acc[2][j] + bs4.z; o.w = acc[3][j] + bs4.w;
        *(float4*)(C + (size_t)(bg * 4 + j) * ldc + n0 + vq * 4) = o;
    }
}

// ---------------- split-K partial GEMM (32 x 64 tile) --------------------------
__global__ void pgemm_kernel(const float* __restrict__ A1, int lda1,
                             const float* __restrict__ W1, int ldw1,
                             const float* __restrict__ A2, int lda2,
                             const float* __restrict__ W2, int ldw2,
                             int slices1, int kPerSlice,
                             float* __restrict__ out, int ldo, int sliceStride)
{
    __shared__ float sxh[TILE_K][33];
    __shared__ float sw[TILE_K][68];
    const int tid = threadIdx.x;  // 128
    const int s = blockIdx.y;
    const int n0 = blockIdx.x * 64;
    const float* a; int la; const float* w; int lw;
    if (s < slices1) { a = A1 + s * kPerSlice; la = lda1; w = W1 + s * kPerSlice; lw = ldw1; }
    else { a = A2; la = lda2; w = W2; lw = ldw2; }
    const int kTiles = kPerSlice / TILE_K;
    const int lb = tid >> 2, lk = (tid & 3) * 4;
    const int ln = tid >> 3, lk8 = (tid & 7) * 4;
    const int vq = tid & 15, bg = tid >> 4;

    float4 ra[2], rw[4];
    #pragma unroll
    for (int it = 0; it < 2; it++)
        ra[it] = *(const float4*)(a + (size_t)lb * la + lk + 16 * it);
    #pragma unroll
    for (int it = 0; it < 4; it++)
        rw[it] = *(const float4*)(w + (size_t)(n0 + ln + 16 * it) * lw + lk8);

    float acc[4][4] = {};
    for (int kt = 0; kt < kTiles; kt++) {
        #pragma unroll
        for (int it = 0; it < 2; it++) {
            int kk = lk + 16 * it;
            sxh[kk + 0][lb] = ra[it].x; sxh[kk + 1][lb] = ra[it].y;
            sxh[kk + 2][lb] = ra[it].z; sxh[kk + 3][lb] = ra[it].w;
        }
        #pragma unroll
        for (int it = 0; it < 4; it++) {
            int n = ln + 16 * it;
            sw[lk8 + 0][n] = rw[it].x; sw[lk8 + 1][n] = rw[it].y;
            sw[lk8 + 2][n] = rw[it].z; sw[lk8 + 3][n] = rw[it].w;
        }
        __syncthreads();
        if (kt + 1 < kTiles) {
            int ko = (kt + 1) * TILE_K;
            #pragma unroll
            for (int it = 0; it < 2; it++)
                ra[it] = *(const float4*)(a + (size_t)lb * la + ko + lk + 16 * it);
            #pragma unroll
            for (int it = 0; it < 4; it++)
                rw[it] = *(const float4*)(w + (size_t)(n0 + ln + 16 * it) * lw + ko + lk8);
        }
        #pragma unroll 8
        for (int k = 0; k < TILE_K; k++) {
            float4 wv = *(const float4*)(&sw[k][vq * 4]);
            float a0 = sxh[k][bg * 4 + 0], a1 = sxh[k][bg * 4 + 1];
            float a2 = sxh[k][bg * 4 + 2], a3 = sxh[k][bg * 4 + 3];
            acc[0][0] += wv.x * a0; acc[0][1] += wv.x * a1; acc[0][2] += wv.x * a2; acc[0][3] += wv.x * a3;
            acc[1][0] += wv.y * a0; acc[1][1] += wv.y * a1; acc[1][2] += wv.y * a2; acc[1][3] += wv.y * a3;
            acc[2][0] += wv.z * a0; acc[2][1] += wv.z * a1; acc[2][2] += wv.z * a2; acc[2][3] += wv.z * a3;
            acc[3][0] += wv.w * a0; acc[3][1] += wv.w * a1; acc[3][2] += wv.w * a2; acc[3][3] += wv.w * a3;
        }
        __syncthreads();
    }
    #pragma unroll
    for (int j = 0; j < 4; j++) {
        int b = bg * 4 + j;
        *(float4*)(out + (size_t)s * sliceStride + (size_t)b * ldo + n0 + vq * 4) =
            make_float4(acc[0][j], acc[1][j], acc[2][j], acc[3][j]);
    }
}

// ---------------- scores: Va.tanh(q+ua) via exp identity -----------------------
__global__ void scores_kernel(const float* __restrict__ Wa_b,
                              const float* __restrict__ Va_w,
                              const float* __restrict__ Va_b)
{
    __shared__ float se[HH], sva[HH];
    const int b = blockIdx.y;
    const int tid = threadIdx.x;  // 256
    for (int i = tid; i < HH; i += 256) {
        float q = g_qp[0 * BB * HH + b * HH + i] + g_qp[1 * BB * HH + b * HH + i]
                + g_qp[2 * BB * HH + b * HH + i] + g_qp[3 * BB * HH + b * HH + i]
                + Wa_b[i];
        se[i] = __expf(2.f * q);
        sva[i] = Va_w[i];
    }
    __syncthreads();
    const int warp = tid >> 5, lane = tid & 31;
    const int s = blockIdx.x * 8 + warp;
    const float* eu = g_eu + (size_t)(b * SS + s) * HH;
    float sum = 0.f;
    #pragma unroll 4
    for (int k = lane; k < HH; k += 32) {
        float t = se[k] * eu[k];
        float r = rcpf(t + 1.f);
        sum += sva[k] * (1.f - 2.f * r);
    }
    #pragma unroll
    for (int o = 16; o; o >>= 1) sum += __shfl_xor_sync(~0u, sum, o);
    if (lane == 0) g_sc[b * SS + s] = sum + Va_b[0];
}

// ---------------- softmax + context --------------------------------------------
__global__ void smax_ctx_kernel(const float* __restrict__ enc,
                                float* __restrict__ attn_out, int t)
{
    __shared__ float sw[SS];
    __shared__ float sms[2];
    const int b = blockIdx.x;
    const int tid = threadIdx.x;  // 256
    if (tid < SS) sw[tid] = g_sc[b * SS + tid];
    __syncthreads();
    if (tid == 0) {
        float m = sw[0];
        for (int s = 1; s < SS; s++) m = fmaxf(m, sw[s]);
        float ss = 0.f;
        for (int s = 0; s < SS; s++) ss += __expf(sw[s] - m);
        sms[0] = m; sms[1] = rcpf(ss);
    }
    __syncthreads();
    if (tid < SS) {
        float w = __expf(sw[tid] - sms[0]) * sms[1];
        sw[tid] = w;
        attn_out[((size_t)b * TT + t) * SS + tid] = w;
    }
    __syncthreads();
    for (int k = tid; k < 2 * HH; k += 256) {
        float a = 0.f;
        #pragma unroll 8
        for (int s = 0; s < SS; s++)
            a += sw[s] * enc[(size_t)(b * SS + s) * (2 * HH) + k];
        g_ctx[b * 2 * HH + k] = a;
    }
}

// ---------------- GRU gates ----------------------------------------------------
__global__ void gates_kernel(const float* __restrict__ gxe_t,
                             const float* __restrict__ b_hh,
                             const float* __restrict__ h_old,
                             float* __restrict__ h_new)
{
    const int b = blockIdx.x;
    const int j = threadIdx.x;  // 512
    const float* p0 = g_part + (size_t)(0 * BB + b) * (3 * HH);
    const float* p1 = g_part + (size_t)(1 * BB + b) * (3 * HH);
    const float* p2 = g_part + (size_t)(2 * BB + b) * (3 * HH);
    const float* ge = gxe_t + (size_t)b * (3 * HH);
    float gx_r = ge[j] + p0[j] + p1[j];
    float gh_r = p2[j] + b_hh[j];
    float gx_z = ge[j + HH] + p0[j + HH] + p1[j + HH];
    float gh_z = p2[j + HH] + b_hh[j + HH];
    float gx_n = ge[j + 2 * HH] + p0[j + 2 * HH] + p1[j + 2 * HH];
    float gh_n = p2[j + 2 * HH] + b_hh[j + 2 * HH];
    float r = sig_f(gx_r + gh_r);
    float z = sig_f(gx_z + gh_z);
    float n = tanh_f(gx_n + r * gh_n);
    h_new[b * HH + j] = (1.f - z) * n + z * h_old[b * HH + j];
}

// ---------------- final log-softmax subtract -----------------------------------
__global__ void lsm_final_kernel(float* __restrict__ logp)
{
    const int r = blockIdx.x;  // 0..1023 = b*TT+t
    __shared__ float sred[8];
    __shared__ float sls;
    const int tid = threadIdx.x;  // 256
    float s = (tid < 250) ? g_psum[(size_t)r * 256 + tid] : 0.f;
    #pragma unroll
    for (int o = 16; o; o >>= 1) s += __shfl_down_sync(~0u, s, o);
    if ((tid & 31) == 0) sred[tid >> 5] = s;
    __syncthreads();
    if (tid == 0) {
        float tot = 0.f;
        for (int w = 0; w < 8; w++) tot += sred[w];
        sls = logf(tot);
    }
    __syncthreads();
    float ls = sls;
    float* row = logp + (size_t)r * VV;
    for (int i = tid * 4; i < VV; i += 1024) {
        float4 v = *(float4*)(row + i);
        v.x -= ls; v.y -= ls; v.z -= ls; v.w -= ls;
        *(float4*)(row + i) = v;
    }
}

__global__ void copy_kernel(const float* __restrict__ src, float* __restrict__ dst, int n)
{
    int i = blockIdx.x * blockDim.x + threadIdx.x;
    if (i < n) dst[i] = src[i];
}

// ---------------- launcher -----------------------------------------------------
extern "C" void kernel_launch(void* const* d_in, const int* in_sizes, int n_in,
                              void* d_out, int out_size)
{
    const float* enc   = (const float*)d_in[0];
    const float* ehid  = (const float*)d_in[1];
    const int*   tgt   = (const int*)  d_in[2];
    const float* emb   = (const float*)d_in[3];
    const float* Wa_w  = (const float*)d_in[4];
    const float* Wa_b  = (const float*)d_in[5];
    const float* Ua_w  = (const float*)d_in[6];
    const float* Ua_b  = (const float*)d_in[7];
    const float* Va_w  = (const float*)d_in[8];
    const float* Va_b  = (const float*)d_in[9];
    const float* W_ih  = (const float*)d_in[10];
    const float* b_ih  = (const float*)d_in[11];
    const float* W_hh  = (const float*)d_in[12];
    const float* b_hh  = (const float*)d_in[13];
    const float* Wh    = (const float*)d_in[14];
    const float* bh    = (const float*)d_in[15];
    const float* out_w = (const float*)d_in[16];
    const float* out_b = (const float*)d_in[17];

    float* outp = (float*)d_out;
    float* logp = outp;
    float* hfin = outp + (size_t)BB * TT * VV;
    float* attn = hfin + (size_t)BB * HH;

    float *hall, *eu, *gxe, *qp, *ctx, *part, *psum;
    int* tokp;
    cudaGetSymbolAddress((void**)&hall, g_Hall);
    cudaGetSymbolAddress((void**)&eu,   g_eu);
    cudaGetSymbolAddress((void**)&gxe,  g_gxe);
    cudaGetSymbolAddress((void**)&qp,   g_qp);
    cudaGetSymbolAddress((void**)&ctx,  g_ctx);
    cudaGetSymbolAddress((void**)&part, g_part);
    cudaGetSymbolAddress((void**)&psum, g_psum);
    cudaGetSymbolAddress((void**)&tokp, g_tok);

    tok_kernel<<<4, 256>>>(tgt);
    // h0 -> slot 0
    gemm_tn_kernel<<<dim3(4, 1), 256>>>(ehid, 2 * HH, Wh, 2 * HH, hall, HH, bh, 2 * HH);
    // e2u = exp(2*(enc@Ua^T + Ua_b))  [2048,512]
    big128_kernel<<<dim3(4, 16), 256>>>(enc, 2 * HH, nullptr, Ua_w, 2 * HH, Ua_b,
                                        2 * HH, eu, HH, 2, nullptr);
    // gxe = emb[tok]@W_ih_emb^T + b_ih  [1024,1536]
    big128_kernel<<<dim3(12, 8), 256>>>(emb, HH, tokp, W_ih, 3 * HH, b_ih,
                                        HH, gxe, 3 * HH, 1, nullptr);

    for (int t = 0; t < TT; t++) {
        float* hcur = hall + (size_t)t * BB * HH;
        float* hnxt = hall + (size_t)(t + 1) * BB * HH;
        // q partials (split-K 4 x 128)
        pgemm_kernel<<<dim3(8, 4), 128>>>(hcur, HH, Wa_w, HH, hcur, HH, Wa_w, HH,
                                          4, 128, qp, HH, BB * HH);
        scores_kernel<<<dim3(8, BB), 256>>>(Wa_b, Va_w, Va_b);
        smax_ctx_kernel<<<BB, 256>>>(enc, attn, t);
        // GRU: ctx (2 slices of 512) + h (W_hh)
        pgemm_kernel<<<dim3(24, 3), 128>>>(ctx, 2 * HH, W_ih + HH, 3 * HH,
                                           hcur, HH, W_hh, HH,
                                           2, HH, part, 3 * HH, BB * 3 * HH);
        gates_kernel<<<BB, HH>>>(gxe + (size_t)t * BB * 3 * HH, b_hh, hcur, hnxt);
    }

    // logits for all steps: A = slots 1..32, fused exp psum, permuted store
    big128_kernel<<<dim3(VV / 128, 8), 256>>>(hall + BB * HH, HH, nullptr,
                                              out_w, HH, out_b, HH,
                                              logp, 0, 0, psum);
    lsm_final_kernel<<<BB * TT, 256>>>(logp);
    copy_kernel<<<16, 1024>>>(hall + (size_t)TT * BB * HH, hfin, BB * HH);
}

// round 4
// speedup vs baseline: 3.6025x; 1.3735x over previous
#include <cuda_runtime.h>
#include <math.h>

#define BB 32
#define SS 64
#define HH 512
#define TT 32
#define VV 32000
#define TILE_K 32

__device__ float g_Hall[(TT + 1) * BB * HH];
__device__ float g_eu[BB * SS * HH];
__device__ float g_gxe[TT * BB * 3 * HH];
__device__ float g_ctx[BB * 2 * HH];
__device__ float g_part[3 * BB * 3 * HH];
__device__ float g_psum[BB * TT * 256];
__device__ int   g_tok[TT * BB];

typedef unsigned long long ull;
__device__ __forceinline__ void ffma2(ull& d, ull a, ull b) {
    asm("fma.rn.f32x2 %0, %1, %2, %0;" : "+l"(d) : "l"(a), "l"(b));
}
__device__ __forceinline__ ull dup2(float x) {
    ull r; asm("mov.b64 %0, {%1, %1};" : "=l"(r) : "f"(x)); return r;
}
__device__ __forceinline__ float2 unpack2(ull v) {
    float2 r; asm("mov.b64 {%0, %1}, %2;" : "=f"(r.x), "=f"(r.y) : "l"(v)); return r;
}
__device__ __forceinline__ float rcpf(float x) {
    float r; asm("rcp.approx.f32 %0, %1;" : "=f"(r) : "f"(x)); return r;
}
__device__ __forceinline__ float sig_f(float x) {
    x = fminf(fmaxf(x, -30.f), 30.f);
    return rcpf(1.f + __expf(-x));
}
__device__ __forceinline__ float tanh_f(float x) {
    x = fminf(fmaxf(x, -15.f), 15.f);
    float e = __expf(2.f * x);
    return 1.f - 2.f * rcpf(e + 1.f);
}

__global__ void tok_kernel(const int* __restrict__ tgt) {
    int i = blockIdx.x * 256 + threadIdx.x;
    if (i < TT * BB) {
        int t = i >> 5, b = i & 31;
        g_tok[i] = (t == 0) ? 0 : tgt[b * TT + t - 1];
    }
}

// grid.x = m-tile, grid.y = n-tile. Register double-buffered, FFMA2 math.
__global__ __launch_bounds__(256, 2)
void big128_kernel(const float* __restrict__ A, int lda,
                   const int* __restrict__ tokens,
                   const float* __restrict__ W, int ldw,
                   const float* __restrict__ bias, int K,
                   float* __restrict__ C, int ldc, int mode,
                   float* __restrict__ psum)
{
    __shared__ __align__(16) float sA[16][132];
    __shared__ __align__(16) float sB[16][132];
    const int tid = threadIdx.x;
    const int m0 = blockIdx.x * 128;
    const int n0 = blockIdx.y * 128;
    const int tx4 = (tid & 15) * 4;
    const int ty4 = (tid >> 4) * 4;

    const int row0 = tid >> 2,         kq0 = (tid & 3) * 4;
    const int row1 = (tid + 256) >> 2, kq1 = kq0;
    long ar0 = tokens ? (long)tokens[m0 + row0] : (long)(m0 + row0);
    long ar1 = tokens ? (long)tokens[m0 + row1] : (long)(m0 + row1);
    const float* ap0 = A + ar0 * lda + kq0;
    const float* ap1 = A + ar1 * lda + kq1;
    const float* wp0 = W + (size_t)(n0 + row0) * ldw + kq0;
    const float* wp1 = W + (size_t)(n0 + row1) * ldw + kq1;

    float4 ra0 = *(const float4*)ap0;
    float4 ra1 = *(const float4*)ap1;
    float4 rw0 = *(const float4*)wp0;
    float4 rw1 = *(const float4*)wp1;

    ull acc[4][8];
    #pragma unroll
    for (int i = 0; i < 4; i++)
        #pragma unroll
        for (int j = 0; j < 8; j++) acc[i][j] = 0ull;

    const int kTiles = K / 16;
    for (int kt = 0; kt < kTiles; kt++) {
        sA[kq0 + 0][row0] = ra0.x; sA[kq0 + 1][row0] = ra0.y;
        sA[kq0 + 2][row0] = ra0.z; sA[kq0 + 3][row0] = ra0.w;
        sA[kq1 + 0][row1] = ra1.x; sA[kq1 + 1][row1] = ra1.y;
        sA[kq1 + 2][row1] = ra1.z; sA[kq1 + 3][row1] = ra1.w;
        sB[kq0 + 0][row0] = rw0.x; sB[kq0 + 1][row0] = rw0.y;
        sB[kq0 + 2][row0] = rw0.z; sB[kq0 + 3][row0] = rw0.w;
        sB[kq1 + 0][row1] = rw1.x; sB[kq1 + 1][row1] = rw1.y;
        sB[kq1 + 2][row1] = rw1.z; sB[kq1 + 3][row1] = rw1.w;
        __syncthreads();
        if (kt + 1 < kTiles) {
            int ko = (kt + 1) * 16;
            ra0 = *(const float4*)(ap0 + ko);
            ra1 = *(const float4*)(ap1 + ko);
            rw0 = *(const float4*)(wp0 + ko);
            rw1 = *(const float4*)(wp1 + ko);
        }
        #pragma unroll
        for (int k = 0; k < 16; k++) {
            ulonglong2 a0 = *(const ulonglong2*)&sA[k][ty4];
            ulonglong2 a1 = *(const ulonglong2*)&sA[k][64 + ty4];
            float4 b0 = *(const float4*)&sB[k][tx4];
            float4 b1 = *(const float4*)&sB[k][64 + tx4];
            ull ap[4] = {a0.x, a0.y, a1.x, a1.y};
            ull bd[8] = {dup2(b0.x), dup2(b0.y), dup2(b0.z), dup2(b0.w),
                         dup2(b1.x), dup2(b1.y), dup2(b1.z), dup2(b1.w)};
            #pragma unroll
            for (int mp = 0; mp < 4; mp++)
                #pragma unroll
                for (int n = 0; n < 8; n++)
                    ffma2(acc[mp][n], ap[mp], bd[n]);
        }
        __syncthreads();
    }

    float4 bs0 = *(const float4*)&bias[n0 + tx4];
    float4 bs1 = *(const float4*)&bias[n0 + 64 + tx4];
    #pragma unroll
    for (int mp = 0; mp < 4; mp++) {
        #pragma unroll
        for (int half = 0; half < 2; half++) {
            int gm = m0 + (mp >> 1) * 64 + ty4 + (mp & 1) * 2 + half;
            float v[8];
            #pragma unroll
            for (int n = 0; n < 8; n++) {
                float2 p = unpack2(acc[mp][n]);
                v[n] = half ? p.y : p.x;
            }
            v[0] += bs0.x; v[1] += bs0.y; v[2] += bs0.z; v[3] += bs0.w;
            v[4] += bs1.x; v[5] += bs1.y; v[6] += bs1.z; v[7] += bs1.w;
            if (mode == 2) {
                #pragma unroll
                for (int n = 0; n < 8; n++) v[n] = __expf(2.f * v[n]);
            }
            float* cp;
            if (mode == 0) {
                int tq = gm >> 5, bq = gm & 31;
                cp = C + (size_t)(bq * TT + tq) * VV + n0;
            } else {
                cp = C + (size_t)gm * ldc + n0;
            }
            *(float4*)(cp + tx4)      = make_float4(v[0], v[1], v[2], v[3]);
            *(float4*)(cp + 64 + tx4) = make_float4(v[4], v[5], v[6], v[7]);
            if (mode == 0) {
                float es = 0.f;
                #pragma unroll
                for (int n = 0; n < 8; n++) es += __expf(v[n]);
                #pragma unroll
                for (int o = 8; o; o >>= 1)
                    es += __shfl_down_sync(0xffffffffu, es, o, 16);
                if ((tid & 15) == 0) {
                    int tq = gm >> 5, bq = gm & 31;
                    psum[(size_t)(bq * TT + tq) * 256 + blockIdx.y] = es;
                }
            }
        }
    }
}

__global__ void gemm_tn_kernel(const float* __restrict__ A, int lda,
                               const float* __restrict__ W, int ldb,
                               float* __restrict__ C, int ldc,
                               const float* __restrict__ bias, int K)
{
    __shared__ float sa[TILE_K][33];
    __shared__ float sb[TILE_K][132];
    const int tid = threadIdx.x;
    const int n0 = blockIdx.x * 128;
    const int vq = tid & 31, bg = tid >> 5;
    const int lm = tid >> 3, lk = (tid & 7) * 4;
    float acc[4][4] = {};
    for (int k0 = 0; k0 < K; k0 += TILE_K) {
        float4 a4 = *(const float4*)(A + (size_t)lm * lda + k0 + lk);
        sa[lk + 0][lm] = a4.x; sa[lk + 1][lm] = a4.y;
        sa[lk + 2][lm] = a4.z; sa[lk + 3][lm] = a4.w;
        #pragma unroll
        for (int it = 0; it < 4; it++) {
            int n = lm + 32 * it;
            float4 b4 = *(const float4*)(W + (size_t)(n0 + n) * ldb + k0 + lk);
            sb[lk + 0][n] = b4.x; sb[lk + 1][n] = b4.y;
            sb[lk + 2][n] = b4.z; sb[lk + 3][n] = b4.w;
        }
        __syncthreads();
        #pragma unroll 8
        for (int k = 0; k < TILE_K; k++) {
            float4 bv = *(const float4*)(&sb[k][vq * 4]);
            float a0 = sa[k][bg * 4 + 0], a1 = sa[k][bg * 4 + 1];
            float a2 = sa[k][bg * 4 + 2], a3 = sa[k][bg * 4 + 3];
            acc[0][0] += bv.x * a0; acc[0][1] += bv.x * a1; acc[0][2] += bv.x * a2; acc[0][3] += bv.x * a3;
            acc[1][0] += bv.y * a0; acc[1][1] += bv.y * a1; acc[1][2] += bv.y * a2; acc[1][3] += bv.y * a3;
            acc[2][0] += bv.z * a0; acc[2][1] += bv.z * a1; acc[2][2] += bv.z * a2; acc[2][3] += bv.z * a3;
            acc[3][0] += bv.w * a0; acc[3][1] += bv.w * a1; acc[3][2] += bv.w * a2; acc[3][3] += bv.w * a3;
        }
        __syncthreads();
    }
    float4 bs4 = *(const float4*)(bias + n0 + vq * 4);
    #pragma unroll
    for (int j = 0; j < 4; j++) {
        float4 o;
        o.x = acc[0][j] + bs4.x; o.y = acc[1][j] + bs4.y;
        o.z = acc[2][j] + bs4.z; o.w = acc[3][j] + bs4.w;
        *(float4*)(C + (size_t)(bg * 4 + j) * ldc + n0 + vq * 4) = o;
    }
}

__global__ void pgemm_kernel(const float* __restrict__ A1, int lda1,
                             const float* __restrict__ W1, int ldw1,
                             const float* __restrict__ A2, int lda2,
                             const float* __restrict__ W2, int ldw2,
                             int slices1, int kPerSlice,
                             float* __restrict__ out, int ldo, int sliceStride)
{
    __shared__ float sxh[TILE_K][33];
    __shared__ float sw[TILE_K][68];
    const int tid = threadIdx.x;
    const int s = blockIdx.y;
    const int n0 = blockIdx.x * 64;
    const float* a; int la; const float* w; int lw;
    if (s < slices1) { a = A1 + s * kPerSlice; la = lda1; w = W1 + s * kPerSlice; lw = ldw1; }
    else { a = A2; la = lda2; w = W2; lw = ldw2; }
    const int kTiles = kPerSlice / TILE_K;
    const int lb = tid >> 2, lk = (tid & 3) * 4;
    const int ln = tid >> 3, lk8 = (tid & 7) * 4;
    const int vq = tid & 15, bg = tid >> 4;

    float4 ra[2], rw[4];
    #pragma unroll
    for (int it = 0; it < 2; it++)
        ra[it] = *(const float4*)(a + (size_t)lb * la + lk + 16 * it);
    #pragma unroll
    for (int it = 0; it < 4; it++)
        rw[it] = *(const float4*)(w + (size_t)(n0 + ln + 16 * it) * lw + lk8);

    float acc[4][4] = {};
    for (int kt = 0; kt < kTiles; kt++) {
        #pragma unroll
        for (int it = 0; it < 2; it++) {
            int kk = lk + 16 * it;
            sxh[kk + 0][lb] = ra[it].x; sxh[kk + 1][lb] = ra[it].y;
            sxh[kk + 2][lb] = ra[it].z; sxh[kk + 3][lb] = ra[it].w;
        }
        #pragma unroll
        for (int it = 0; it < 4; it++) {
            int n = ln + 16 * it;
            sw[lk8 + 0][n] = rw[it].x; sw[lk8 + 1][n] = rw[it].y;
            sw[lk8 + 2][n] = rw[it].z; sw[lk8 + 3][n] = rw[it].w;
        }
        __syncthreads();
        if (kt + 1 < kTiles) {
            int ko = (kt + 1) * TILE_K;
            #pragma unroll
            for (int it = 0; it < 2; it++)
                ra[it] = *(const float4*)(a + (size_t)lb * la + ko + lk + 16 * it);
            #pragma unroll
            for (int it = 0; it < 4; it++)
                rw[it] = *(const float4*)(w + (size_t)(n0 + ln + 16 * it) * lw + ko + lk8);
        }
        #pragma unroll 8
        for (int k = 0; k < TILE_K; k++) {
            float4 wv = *(const float4*)(&sw[k][vq * 4]);
            float a0 = sxh[k][bg * 4 + 0], a1 = sxh[k][bg * 4 + 1];
            float a2 = sxh[k][bg * 4 + 2], a3 = sxh[k][bg * 4 + 3];
            acc[0][0] += wv.x * a0; acc[0][1] += wv.x * a1; acc[0][2] += wv.x * a2; acc[0][3] += wv.x * a3;
            acc[1][0] += wv.y * a0; acc[1][1] += wv.y * a1; acc[1][2] += wv.y * a2; acc[1][3] += wv.y * a3;
            acc[2][0] += wv.z * a0; acc[2][1] += wv.z * a1; acc[2][2] += wv.z * a2; acc[2][3] += wv.z * a3;
            acc[3][0] += wv.w * a0; acc[3][1] += wv.w * a1; acc[3][2] += wv.w * a2; acc[3][3] += wv.w * a3;
        }
        __syncthreads();
    }
    #pragma unroll
    for (int j = 0; j < 4; j++) {
        int b = bg * 4 + j;
        *(float4*)(out + (size_t)s * sliceStride + (size_t)b * ldo + n0 + vq * 4) =
            make_float4(acc[0][j], acc[1][j], acc[2][j], acc[3][j]);
    }
}

// fused per-step: gates(t-1) -> h_t, then q, scores, softmax, ctx. grid=BB, block=512
__global__ void attn_step_kernel(const float* __restrict__ Wa_w,
                                 const float* __restrict__ Wa_b,
                                 const float* __restrict__ Va_w,
                                 const float* __restrict__ Va_b,
                                 const float* __restrict__ enc,
                                 const float* __restrict__ b_hh,
                                 float* __restrict__ attn_out, int t)
{
    __shared__ __align__(16) float sh_h[HH];
    __shared__ __align__(16) float se[HH];
    __shared__ __align__(16) float sva[HH];
    __shared__ float ssc[SS];
    __shared__ float sms[2];
    const int b = blockIdx.x;
    const int tid = threadIdx.x;
    const int warp = tid >> 5, lane = tid & 31;

    if (t > 0) {
        const int j = tid;
        const float* p0 = g_part + (size_t)(0 * BB + b) * (3 * HH);
        const float* p1 = g_part + (size_t)(1 * BB + b) * (3 * HH);
        const float* p2 = g_part + (size_t)(2 * BB + b) * (3 * HH);
        const float* ge = g_gxe + ((size_t)(t - 1) * BB + b) * (3 * HH);
        float gx_r = ge[j] + p0[j] + p1[j];
        float gh_r = p2[j] + b_hh[j];
        float gx_z = ge[j + HH] + p0[j + HH] + p1[j + HH];
        float gh_z = p2[j + HH] + b_hh[j + HH];
        float gx_n = ge[j + 2 * HH] + p0[j + 2 * HH] + p1[j + 2 * HH];
        float gh_n = p2[j + 2 * HH] + b_hh[j + 2 * HH];
        float r = sig_f(gx_r + gh_r);
        float z = sig_f(gx_z + gh_z);
        float n = tanh_f(gx_n + r * gh_n);
        float hp = g_Hall[(size_t)(t - 1) * BB * HH + b * HH + j];
        float hn = (1.f - z) * n + z * hp;
        sh_h[j] = hn;
        g_Hall[(size_t)t * BB * HH + b * HH + j] = hn;
    } else {
        sh_h[tid] = g_Hall[b * HH + tid];
    }
    sva[tid] = Va_w[tid];
    __syncthreads();

    const float4* sh4 = (const float4*)sh_h;
    for (int rr = 0; rr < 32; rr++) {
        int i = warp * 32 + rr;
        const float4* wrow = (const float4*)(Wa_w + (size_t)i * HH);
        float sum = 0.f;
        #pragma unroll
        for (int it = 0; it < 4; it++) {
            int idx = lane + 32 * it;
            float4 w4 = wrow[idx];
            float4 h4 = sh4[idx];
            sum += w4.x * h4.x + w4.y * h4.y + w4.z * h4.z + w4.w * h4.w;
        }
        #pragma unroll
        for (int o = 16; o; o >>= 1) sum += __shfl_xor_sync(~0u, sum, o);
        if (lane == 0) se[i] = __expf(2.f * (sum + Wa_b[i]));
    }
    __syncthreads();

    const float4* se4 = (const float4*)se;
    const float4* sva4 = (const float4*)sva;
    for (int ss = 0; ss < 4; ss++) {
        int s = warp * 4 + ss;
        const float4* eu = (const float4*)(g_eu + (size_t)(b * SS + s) * HH);
        float sum = 0.f;
        #pragma unroll
        for (int it = 0; it < 4; it++) {
            int idx = lane + 32 * it;
            float4 e4 = eu[idx];
            float4 q4 = se4[idx];
            float4 v4 = sva4[idx];
            sum += v4.x * (1.f - 2.f * rcpf(q4.x * e4.x + 1.f));
            sum += v4.y * (1.f - 2.f * rcpf(q4.y * e4.y + 1.f));
            sum += v4.z * (1.f - 2.f * rcpf(q4.z * e4.z + 1.f));
            sum += v4.w * (1.f - 2.f * rcpf(q4.w * e4.w + 1.f));
        }
        #pragma unroll
        for (int o = 16; o; o >>= 1) sum += __shfl_xor_sync(~0u, sum, o);
        if (lane == 0) ssc[s] = sum + Va_b[0];
    }
    __syncthreads();

    if (tid == 0) {
        float m = ssc[0];
        for (int s = 1; s < SS; s++) m = fmaxf(m, ssc[s]);
        float sm = 0.f;
        for (int s = 0; s < SS; s++) sm += __expf(ssc[s] - m);
        sms[0] = m; sms[1] = rcpf(sm);
    }
    __syncthreads();
    if (tid < SS) {
        float w = __expf(ssc[tid] - sms[0]) * sms[1];
        ssc[tid] = w;
        attn_out[((size_t)b * TT + t) * SS + tid] = w;
    }
    __syncthreads();

    for (int kk = tid; kk < 2 * HH; kk += 512) {
        float a = 0.f;
        #pragma unroll 8
        for (int s = 0; s < SS; s++)
            a += ssc[s] * enc[(size_t)(b * SS + s) * (2 * HH) + kk];
        g_ctx[b * 2 * HH + kk] = a;
    }
}

__global__ void gates_kernel(const float* __restrict__ gxe_t,
                             const float* __restrict__ b_hh,
                             const float* __restrict__ h_old,
                             float* __restrict__ h_new,
                             float* __restrict__ h_new2)
{
    const int b = blockIdx.x;
    const int j = threadIdx.x;
    const float* p0 = g_part + (size_t)(0 * BB + b) * (3 * HH);
    const float* p1 = g_part + (size_t)(1 * BB + b) * (3 * HH);
    const float* p2 = g_part + (size_t)(2 * BB + b) * (3 * HH);
    const float* ge = gxe_t + (size_t)b * (3 * HH);
    float gx_r = ge[j] + p0[j] + p1[j];
    float gh_r = p2[j] + b_hh[j];
    float gx_z = ge[j + HH] + p0[j + HH] + p1[j + HH];
    float gh_z = p2[j + HH] + b_hh[j + HH];
    float gx_n = ge[j + 2 * HH] + p0[j + 2 * HH] + p1[j + 2 * HH];
    float gh_n = p2[j + 2 * HH] + b_hh[j + 2 * HH];
    float r = sig_f(gx_r + gh_r);
    float z = sig_f(gx_z + gh_z);
    float n = tanh_f(gx_n + r * gh_n);
    float hv = (1.f - z) * n + z * h_old[b * HH + j];
    h_new[b * HH + j] = hv;
    h_new2[b * HH + j] = hv;
}

__global__ void lsm_final_kernel(float* __restrict__ logp)
{
    const int r = blockIdx.x;
    __shared__ float sred[8];
    __shared__ float sls;
    const int tid = threadIdx.x;
    float s = (tid < 250) ? g_psum[(size_t)r * 256 + tid] : 0.f;
    #pragma unroll
    for (int o = 16; o; o >>= 1) s += __shfl_down_sync(~0u, s, o);
    if ((tid & 31) == 0) sred[tid >> 5] = s;
    __syncthreads();
    if (tid == 0) {
        float tot = 0.f;
        for (int w = 0; w < 8; w++) tot += sred[w];
        sls = logf(tot);
    }
    __syncthreads();
    float ls = sls;
    float* row = logp + (size_t)r * VV;
    for (int i = tid * 4; i < VV; i += 1024) {
        float4 v = *(float4*)(row + i);
        v.x -= ls; v.y -= ls; v.z -= ls; v.w -= ls;
        *(float4*)(row + i) = v;
    }
}

extern "C" void kernel_launch(void* const* d_in, const int* in_sizes, int n_in,
                              void* d_out, int out_size)
{
    const float* enc   = (const float*)d_in[0];
    const float* ehid  = (const float*)d_in[1];
    const int*   tgt   = (const int*)  d_in[2];
    const float* emb   = (const float*)d_in[3];
    const float* Wa_w  = (const float*)d_in[4];
    const float* Wa_b  = (const float*)d_in[5];
    const float* Ua_w  = (const float*)d_in[6];
    const float* Ua_b  = (const float*)d_in[7];
    const float* Va_w  = (const float*)d_in[8];
    const float* Va_b  = (const float*)d_in[9];
    const float* W_ih  = (const float*)d_in[10];
    const float* b_ih  = (const float*)d_in[11];
    const float* W_hh  = (const float*)d_in[12];
    const float* b_hh  = (const float*)d_in[13];
    const float* Wh    = (const float*)d_in[14];
    const float* bh    = (const float*)d_in[15];
    const float* out_w = (const float*)d_in[16];
    const float* out_b = (const float*)d_in[17];

    float* outp = (float*)d_out;
    float* logp = outp;
    float* hfin = outp + (size_t)BB * TT * VV;
    float* attn = hfin + (size_t)BB * HH;

    float *hall, *eu, *gxe, *ctx, *part, *psum;
    int* tokp;
    cudaGetSymbolAddress((void**)&hall, g_Hall);
    cudaGetSymbolAddress((void**)&eu,   g_eu);
    cudaGetSymbolAddress((void**)&gxe,  g_gxe);
    cudaGetSymbolAddress((void**)&ctx,  g_ctx);
    cudaGetSymbolAddress((void**)&part, g_part);
    cudaGetSymbolAddress((void**)&psum, g_psum);
    cudaGetSymbolAddress((void**)&tokp, g_tok);

    tok_kernel<<<4, 256>>>(tgt);
    gemm_tn_kernel<<<dim3(4, 1), 256>>>(ehid, 2 * HH, Wh, 2 * HH, hall, HH, bh, 2 * HH);
    big128_kernel<<<dim3(16, 4), 256>>>(enc, 2 * HH, nullptr, Ua_w, 2 * HH, Ua_b,
                                        2 * HH, eu, HH, 2, nullptr);
    big128_kernel<<<dim3(8, 12), 256>>>(emb, HH, tokp, W_ih, 3 * HH, b_ih,
                                        HH, gxe, 3 * HH, 1, nullptr);

    for (int t = 0; t < TT; t++) {
        float* hcur = hall + (size_t)t * BB * HH;
        attn_step_kernel<<<BB, 512>>>(Wa_w, Wa_b, Va_w, Va_b, enc, b_hh, attn, t);
        pgemm_kernel<<<dim3(24, 3), 128>>>(ctx, 2 * HH, W_ih + HH, 3 * HH,
                                           hcur, HH, W_hh, HH,
                                           2, HH, part, 3 * HH, BB * 3 * HH);
    }
    // final gates -> h_32 into slot 32 AND hfin (before logits reads slots 1..32)
    gates_kernel<<<BB, 512>>>(gxe + (size_t)31 * BB * 3 * HH, b_hh,
                              hall + (size_t)31 * BB * HH,
                              hall + (size_t)32 * BB * HH, hfin);

    big128_kernel<<<dim3(8, 250), 256>>>(hall + BB * HH, HH, nullptr,
                                         out_w, HH, out_b, HH,
                                         logp, 0, 0, psum);
    lsm_final_kernel<<<BB * TT, 256>>>(logp);
}

// round 6
// speedup vs baseline: 4.4795x; 1.2435x over previous
#include <cuda_runtime.h>
#include <cuda_bf16.h>
#include <math.h>
#include <stdint.h>

#define BB 32
#define SS 64
#define HH 512
#define TT 32
#define VV 32000
#define TILE_K 32

// ---------------- device scratch ------------------------------------------------
__device__ float g_Hall[(TT + 1) * BB * HH];
__device__ float g_eu[BB * SS * HH];
__device__ float g_gxe[TT * BB * 3 * HH];
__device__ float g_ctx[BB * 2 * HH];
__device__ float g_part[3 * BB * 3 * HH];
__device__ float g_psum[(size_t)BB * TT * 1024];
__device__ int   g_tok[TT * BB];
__device__ __nv_bfloat16 g_Hbf[TT * BB * HH];      // h_1..h_32 in bf16
__device__ __nv_bfloat16 g_Wbf[(size_t)VV * HH];   // out_w in bf16

typedef unsigned long long ull;
__device__ __forceinline__ void ffma2(ull& d, ull a, ull b) {
    asm("fma.rn.f32x2 %0, %1, %2, %0;" : "+l"(d) : "l"(a), "l"(b));
}
__device__ __forceinline__ ull dup2(float x) {
    ull r; asm("mov.b64 %0, {%1, %1};" : "=l"(r) : "f"(x)); return r;
}
__device__ __forceinline__ float2 unpack2(ull v) {
    float2 r; asm("mov.b64 {%0, %1}, %2;" : "=f"(r.x), "=f"(r.y) : "l"(v)); return r;
}
__device__ __forceinline__ float rcpf(float x) {
    float r; asm("rcp.approx.f32 %0, %1;" : "=f"(r) : "f"(x)); return r;
}
__device__ __forceinline__ float sig_f(float x) {
    x = fminf(fmaxf(x, -30.f), 30.f);
    return rcpf(1.f + __expf(-x));
}
__device__ __forceinline__ float tanh_f(float x) {
    x = fminf(fmaxf(x, -15.f), 15.f);
    float e = __expf(2.f * x);
    return 1.f - 2.f * rcpf(e + 1.f);
}
__device__ __forceinline__ uint32_t cvt_bf16x2(float hi, float lo) {
    uint32_t r;
    asm("cvt.rn.bf16x2.f32 %0, %1, %2;" : "=r"(r) : "f"(hi), "f"(lo));
    return r;
}

// mma.sync m16n8k16 bf16 -> f32 (plain PTX, supported on sm_80+; no arch-a feature)
__device__ __forceinline__ void mma16816(float* d, const uint32_t* a, const uint32_t* b) {
    asm volatile(
        "mma.sync.aligned.m16n8k16.row.col.f32.bf16.bf16.f32 "
        "{%0,%1,%2,%3}, {%4,%5,%6,%7}, {%8,%9}, {%0,%1,%2,%3};"
        : "+f"(d[0]), "+f"(d[1]), "+f"(d[2]), "+f"(d[3])
        : "r"(a[0]), "r"(a[1]), "r"(a[2]), "r"(a[3]), "r"(b[0]), "r"(b[1]));
}

// ---------------- bf16 converts ---------------------------------------------------
__global__ void conv_bf16_kernel(const float* __restrict__ src,
                                 __nv_bfloat16* __restrict__ dst, int n4)
{
    for (int i = blockIdx.x * blockDim.x + threadIdx.x; i < n4; i += gridDim.x * blockDim.x) {
        float4 v = *(const float4*)(src + (size_t)i * 4);
        uint2 o;
        o.x = cvt_bf16x2(v.y, v.x);
        o.y = cvt_bf16x2(v.w, v.z);
        *(uint2*)(dst + (size_t)i * 4) = o;
    }
}

// ---------------- tokens ----------------------------------------------------------
__global__ void tok_kernel(const int* __restrict__ tgt) {
    int i = blockIdx.x * 256 + threadIdx.x;
    if (i < TT * BB) {
        int t = i >> 5, b = i & 31;
        g_tok[i] = (t == 0) ? 0 : tgt[b * TT + t - 1];
    }
}

// ---------------- logits: bf16 HMMA GEMM + fused exp psum -------------------------
// D[1024,32000] = H[1024,512] @ W[32000,512]^T + bias.
// grid (8 m-tiles, 250 n-tiles), block 256 (8 warps: 2 M x 4 N, warp tile 64x32).
#define SPAD 40   // smem row stride in bf16 elems (80 B) -> conflict-free quads
__global__ __launch_bounds__(256)
void logits_hmma_kernel(const __nv_bfloat16* __restrict__ Hbf,
                        const __nv_bfloat16* __restrict__ Wbf,
                        const float* __restrict__ out_b,
                        float* __restrict__ logp, float* __restrict__ psum)
{
    __shared__ __align__(16) __nv_bfloat16 sA[128 * SPAD];
    __shared__ __align__(16) __nv_bfloat16 sB[128 * SPAD];
    __shared__ float sbias[128];
    const int tid = threadIdx.x;
    const int wid = tid >> 5, lane = tid & 31;
    const int m0 = blockIdx.x * 128;
    const int n0 = blockIdx.y * 128;
    if (tid < 128) sbias[tid] = out_b[n0 + tid];

    // global loaders: 2 x 16B per thread per matrix per k-tile
    const int lrow = tid >> 2;        // 0..63
    const int lc = tid & 3;           // 16B chunk within 64B k-slab
    const __nv_bfloat16* Ag0 = Hbf + (size_t)(m0 + lrow) * HH + lc * 8;
    const __nv_bfloat16* Ag1 = Ag0 + (size_t)64 * HH;
    const __nv_bfloat16* Bg0 = Wbf + (size_t)(n0 + lrow) * HH + lc * 8;
    const __nv_bfloat16* Bg1 = Bg0 + (size_t)64 * HH;
    __nv_bfloat16* sA0 = sA + lrow * SPAD + lc * 8;
    __nv_bfloat16* sA1 = sA0 + 64 * SPAD;
    __nv_bfloat16* sB0 = sB + lrow * SPAD + lc * 8;
    __nv_bfloat16* sB1 = sB0 + 64 * SPAD;

    uint4 ra0 = *(const uint4*)Ag0;
    uint4 ra1 = *(const uint4*)Ag1;
    uint4 rb0 = *(const uint4*)Bg0;
    uint4 rb1 = *(const uint4*)Bg1;

    // compute-side bases
    const int mw = (wid >> 2) * 64, nw = (wid & 3) * 32;
    const int qr = lane >> 2, qc = lane & 3;
    const __nv_bfloat16* pa = sA + (mw + qr) * SPAD + qc * 2;
    const __nv_bfloat16* pb = sB + (nw + qr) * SPAD + qc * 2;

    float acc[4][4][4];
    #pragma unroll
    for (int i = 0; i < 4; i++)
        #pragma unroll
        for (int j = 0; j < 4; j++)
            #pragma unroll
            for (int e = 0; e < 4; e++) acc[i][j][e] = 0.f;

    #pragma unroll 1
    for (int kt = 0; kt < 16; kt++) {
        *(uint4*)sA0 = ra0; *(uint4*)sA1 = ra1;
        *(uint4*)sB0 = rb0; *(uint4*)sB1 = rb1;
        __syncthreads();
        if (kt < 15) {
            ra0 = *(const uint4*)(Ag0 + (kt + 1) * 32);
            ra1 = *(const uint4*)(Ag1 + (kt + 1) * 32);
            rb0 = *(const uint4*)(Bg0 + (kt + 1) * 32);
            rb1 = *(const uint4*)(Bg1 + (kt + 1) * 32);
        }
        #pragma unroll
        for (int ks = 0; ks < 2; ks++) {
            uint32_t af[4][4], bf[4][2];
            #pragma unroll
            for (int mi = 0; mi < 4; mi++) {
                const __nv_bfloat16* p = pa + mi * 16 * SPAD + ks * 16;
                af[mi][0] = *(const uint32_t*)(p);
                af[mi][1] = *(const uint32_t*)(p + 8 * SPAD);
                af[mi][2] = *(const uint32_t*)(p + 8);
                af[mi][3] = *(const uint32_t*)(p + 8 * SPAD + 8);
            }
            #pragma unroll
            for (int ni = 0; ni < 4; ni++) {
                const __nv_bfloat16* p = pb + ni * 8 * SPAD + ks * 16;
                bf[ni][0] = *(const uint32_t*)(p);
                bf[ni][1] = *(const uint32_t*)(p + 8);
            }
            #pragma unroll
            for (int mi = 0; mi < 4; mi++)
                #pragma unroll
                for (int ni = 0; ni < 4; ni++)
                    mma16816(acc[mi][ni], af[mi], bf[ni]);
        }
        __syncthreads();
    }

    // epilogue: bias + store (permuted rows) + exp row-partials
    float es[8];
    #pragma unroll
    for (int i = 0; i < 8; i++) es[i] = 0.f;

    #pragma unroll
    for (int mi = 0; mi < 4; mi++) {
        const int rA = m0 + mw + mi * 16 + qr;        // global m of c0,c1
        const int rB = rA + 8;                        // global m of c2,c3
        const int tqA = rA >> 5, bqA = rA & 31;
        const int tqB = rB >> 5, bqB = rB & 31;
        float* cpA = logp + (size_t)(bqA * TT + tqA) * VV + n0;
        float* cpB = logp + (size_t)(bqB * TT + tqB) * VV + n0;
        #pragma unroll
        for (int ni = 0; ni < 4; ni++) {
            const int cl = nw + ni * 8 + qc * 2;      // local col in [0,128)
            float v0 = acc[mi][ni][0] + sbias[cl];
            float v1 = acc[mi][ni][1] + sbias[cl + 1];
            float v2 = acc[mi][ni][2] + sbias[cl];
            float v3 = acc[mi][ni][3] + sbias[cl + 1];
            *(float2*)(cpA + cl) = make_float2(v0, v1);
            *(float2*)(cpB + cl) = make_float2(v2, v3);
            es[mi * 2 + 0] += __expf(v0) + __expf(v1);
            es[mi * 2 + 1] += __expf(v2) + __expf(v3);
        }
    }
    // quad reduce (lanes sharing qr): xor over the two low lane bits
    #pragma unroll
    for (int i = 0; i < 8; i++) {
        es[i] += __shfl_xor_sync(0xffffffffu, es[i], 1);
        es[i] += __shfl_xor_sync(0xffffffffu, es[i], 2);
    }
    if (qc == 0) {
        const int col = blockIdx.y * 4 + (wid & 3);
        #pragma unroll
        for (int mi = 0; mi < 4; mi++) {
            int rA = m0 + mw + mi * 16 + qr;
            int rB = rA + 8;
            int rowA = (rA & 31) * TT + (rA >> 5);
            int rowB = (rB & 31) * TT + (rB >> 5);
            psum[(size_t)rowA * 1024 + col] = es[mi * 2 + 0];
            psum[(size_t)rowB * 1024 + col] = es[mi * 2 + 1];
        }
    }
}

// ---------------- fp32 big GEMM (e2u / gxe), register double-buffered -------------
__global__ __launch_bounds__(256, 2)
void big128_kernel(const float* __restrict__ A, int lda,
                   const int* __restrict__ tokens,
                   const float* __restrict__ W, int ldw,
                   const float* __restrict__ bias, int K,
                   float* __restrict__ C, int ldc, int mode)
{
    __shared__ __align__(16) float sA[16][132];
    __shared__ __align__(16) float sB[16][132];
    const int tid = threadIdx.x;
    const int m0 = blockIdx.x * 128;
    const int n0 = blockIdx.y * 128;
    const int tx4 = (tid & 15) * 4;
    const int ty4 = (tid >> 4) * 4;

    const int row0 = tid >> 2,         kq0 = (tid & 3) * 4;
    const int row1 = (tid + 256) >> 2;
    long ar0 = tokens ? (long)tokens[m0 + row0] : (long)(m0 + row0);
    long ar1 = tokens ? (long)tokens[m0 + row1] : (long)(m0 + row1);
    const float* ap0 = A + ar0 * lda + kq0;
    const float* ap1 = A + ar1 * lda + kq0;
    const float* wp0 = W + (size_t)(n0 + row0) * ldw + kq0;
    const float* wp1 = W + (size_t)(n0 + row1) * ldw + kq0;

    float4 ra0 = *(const float4*)ap0;
    float4 ra1 = *(const float4*)ap1;
    float4 rw0 = *(const float4*)wp0;
    float4 rw1 = *(const float4*)wp1;

    ull acc[4][8];
    #pragma unroll
    for (int i = 0; i < 4; i++)
        #pragma unroll
        for (int j = 0; j < 8; j++) acc[i][j] = 0ull;

    const int kTiles = K / 16;
    for (int kt = 0; kt < kTiles; kt++) {
        sA[kq0 + 0][row0] = ra0.x; sA[kq0 + 1][row0] = ra0.y;
        sA[kq0 + 2][row0] = ra0.z; sA[kq0 + 3][row0] = ra0.w;
        sA[kq0 + 0][row1] = ra1.x; sA[kq0 + 1][row1] = ra1.y;
        sA[kq0 + 2][row1] = ra1.z; sA[kq0 + 3][row1] = ra1.w;
        sB[kq0 + 0][row0] = rw0.x; sB[kq0 + 1][row0] = rw0.y;
        sB[kq0 + 2][row0] = rw0.z; sB[kq0 + 3][row0] = rw0.w;
        sB[kq0 + 0][row1] = rw1.x; sB[kq0 + 1][row1] = rw1.y;
        sB[kq0 + 2][row1] = rw1.z; sB[kq0 + 3][row1] = rw1.w;
        __syncthreads();
        if (kt + 1 < kTiles) {
            int ko = (kt + 1) * 16;
            ra0 = *(const float4*)(ap0 + ko);
            ra1 = *(const float4*)(ap1 + ko);
            rw0 = *(const float4*)(wp0 + ko);
            rw1 = *(const float4*)(wp1 + ko);
        }
        #pragma unroll
        for (int k = 0; k < 16; k++) {
            ulonglong2 a0 = *(const ulonglong2*)&sA[k][ty4];
            ulonglong2 a1 = *(const ulonglong2*)&sA[k][64 + ty4];
            float4 b0 = *(const float4*)&sB[k][tx4];
            float4 b1 = *(const float4*)&sB[k][64 + tx4];
            ull ap[4] = {a0.x, a0.y, a1.x, a1.y};
            ull bd[8] = {dup2(b0.x), dup2(b0.y), dup2(b0.z), dup2(b0.w),
                         dup2(b1.x), dup2(b1.y), dup2(b1.z), dup2(b1.w)};
            #pragma unroll
            for (int mp = 0; mp < 4; mp++)
                #pragma unroll
                for (int n = 0; n < 8; n++)
                    ffma2(acc[mp][n], ap[mp], bd[n]);
        }
        __syncthreads();
    }

    float4 bs0 = *(const float4*)&bias[n0 + tx4];
    float4 bs1 = *(const float4*)&bias[n0 + 64 + tx4];
    #pragma unroll
    for (int mp = 0; mp < 4; mp++) {
        #pragma unroll
        for (int half = 0; half < 2; half++) {
            int gm = m0 + (mp >> 1) * 64 + ty4 + (mp & 1) * 2 + half;
            float v[8];
            #pragma unroll
            for (int n = 0; n < 8; n++) {
                float2 p = unpack2(acc[mp][n]);
                v[n] = half ? p.y : p.x;
            }
            v[0] += bs0.x; v[1] += bs0.y; v[2] += bs0.z; v[3] += bs0.w;
            v[4] += bs1.x; v[5] += bs1.y; v[6] += bs1.z; v[7] += bs1.w;
            if (mode == 2) {
                #pragma unroll
                for (int n = 0; n < 8; n++) v[n] = __expf(2.f * v[n]);
            }
            float* cp = C + (size_t)gm * ldc + n0;
            *(float4*)(cp + tx4)      = make_float4(v[0], v[1], v[2], v[3]);
            *(float4*)(cp + 64 + tx4) = make_float4(v[4], v[5], v[6], v[7]);
        }
    }
}

// ---------------- small gemm (h0 only) --------------------------------------------
__global__ void gemm_tn_kernel(const float* __restrict__ A, int lda,
                               const float* __restrict__ W, int ldb,
                               float* __restrict__ C, int ldc,
                               const float* __restrict__ bias, int K)
{
    __shared__ float sa[TILE_K][33];
    __shared__ float sb[TILE_K][132];
    const int tid = threadIdx.x;
    const int n0 = blockIdx.x * 128;
    const int vq = tid & 31, bg = tid >> 5;
    const int lm = tid >> 3, lk = (tid & 7) * 4;
    float acc[4][4] = {};
    for (int k0 = 0; k0 < K; k0 += TILE_K) {
        float4 a4 = *(const float4*)(A + (size_t)lm * lda + k0 + lk);
        sa[lk + 0][lm] = a4.x; sa[lk + 1][lm] = a4.y;
        sa[lk + 2][lm] = a4.z; sa[lk + 3][lm] = a4.w;
        #pragma unroll
        for (int it = 0; it < 4; it++) {
            int n = lm + 32 * it;
            float4 b4 = *(const float4*)(W + (size_t)(n0 + n) * ldb + k0 + lk);
            sb[lk + 0][n] = b4.x; sb[lk + 1][n] = b4.y;
            sb[lk + 2][n] = b4.z; sb[lk + 3][n] = b4.w;
        }
        __syncthreads();
        #pragma unroll 8
        for (int k = 0; k < TILE_K; k++) {
            float4 bv = *(const float4*)(&sb[k][vq * 4]);
            float a0 = sa[k][bg * 4 + 0], a1 = sa[k][bg * 4 + 1];
            float a2 = sa[k][bg * 4 + 2], a3 = sa[k][bg * 4 + 3];
            acc[0][0] += bv.x * a0; acc[0][1] += bv.x * a1; acc[0][2] += bv.x * a2; acc[0][3] += bv.x * a3;
            acc[1][0] += bv.y * a0; acc[1][1] += bv.y * a1; acc[1][2] += bv.y * a2; acc[1][3] += bv.y * a3;
            acc[2][0] += bv.z * a0; acc[2][1] += bv.z * a1; acc[2][2] += bv.z * a2; acc[2][3] += bv.z * a3;
            acc[3][0] += bv.w * a0; acc[3][1] += bv.w * a1; acc[3][2] += bv.w * a2; acc[3][3] += bv.w * a3;
        }
        __syncthreads();
    }
    float4 bs4 = *(const float4*)(bias + n0 + vq * 4);
    #pragma unroll
    for (int j = 0; j < 4; j++) {
        float4 o;
        o.x = acc[0][j] + bs4.x; o.y = acc[1][j] + bs4.y;
        o.z = acc[2][j] + bs4.z; o.w = acc[3][j] + bs4.w;
        *(float4*)(C + (size_t)(bg * 4 + j) * ldc + n0 + vq * 4) = o;
    }
}

// ---------------- split-K partial GEMM (loop GRU) ----------------------------------
__global__ void pgemm_kernel(const float* __restrict__ A1, int lda1,
                             const float* __restrict__ W1, int ldw1,
                             const float* __restrict__ A2, int lda2,
                             const float* __restrict__ W2, int ldw2,
                             int slices1, int kPerSlice,
                             float* __restrict__ out, int ldo, int sliceStride)
{
    __shared__ float sxh[TILE_K][33];
    __shared__ float sw[TILE_K][68];
    const int tid = threadIdx.x;
    const int s = blockIdx.y;
    const int n0 = blockIdx.x * 64;
    const float* a; int la; const float* w; int lw;
    if (s < slices1) { a = A1 + s * kPerSlice; la = lda1; w = W1 + s * kPerSlice; lw = ldw1; }
    else { a = A2; la = lda2; w = W2; lw = ldw2; }
    const int kTiles = kPerSlice / TILE_K;
    const int lb = tid >> 2, lk = (tid & 3) * 4;
    const int ln = tid >> 3, lk8 = (tid & 7) * 4;
    const int vq = tid & 15, bg = tid >> 4;

    float4 ra[2], rw[4];
    #pragma unroll
    for (int it = 0; it < 2; it++)
        ra[it] = *(const float4*)(a + (size_t)lb * la + lk + 16 * it);
    #pragma unroll
    for (int it = 0; it < 4; it++)
        rw[it] = *(const float4*)(w + (size_t)(n0 + ln + 16 * it) * lw + lk8);

    float acc[4][4] = {};
    for (int kt = 0; kt < kTiles; kt++) {
        #pragma unroll
        for (int it = 0; it < 2; it++) {
            int kk = lk + 16 * it;
            sxh[kk + 0][lb] = ra[it].x; sxh[kk + 1][lb] = ra[it].y;
            sxh[kk + 2][lb] = ra[it].z; sxh[kk + 3][lb] = ra[it].w;
        }
        #pragma unroll
        for (int it = 0; it < 4; it++) {
            int n = ln + 16 * it;
            sw[lk8 + 0][n] = rw[it].x; sw[lk8 + 1][n] = rw[it].y;
            sw[lk8 + 2][n] = rw[it].z; sw[lk8 + 3][n] = rw[it].w;
        }
        __syncthreads();
        if (kt + 1 < kTiles) {
            int ko = (kt + 1) * TILE_K;
            #pragma unroll
            for (int it = 0; it < 2; it++)
                ra[it] = *(const float4*)(a + (size_t)lb * la + ko + lk + 16 * it);
            #pragma unroll
            for (int it = 0; it < 4; it++)
                rw[it] = *(const float4*)(w + (size_t)(n0 + ln + 16 * it) * lw + ko + lk8);
        }
        #pragma unroll 8
        for (int k = 0; k < TILE_K; k++) {
            float4 wv = *(const float4*)(&sw[k][vq * 4]);
            float a0 = sxh[k][bg * 4 + 0], a1 = sxh[k][bg * 4 + 1];
            float a2 = sxh[k][bg * 4 + 2], a3 = sxh[k][bg * 4 + 3];
            acc[0][0] += wv.x * a0; acc[0][1] += wv.x * a1; acc[0][2] += wv.x * a2; acc[0][3] += wv.x * a3;
            acc[1][0] += wv.y * a0; acc[1][1] += wv.y * a1; acc[1][2] += wv.y * a2; acc[1][3] += wv.y * a3;
            acc[2][0] += wv.z * a0; acc[2][1] += wv.z * a1; acc[2][2] += wv.z * a2; acc[2][3] += wv.z * a3;
            acc[3][0] += wv.w * a0; acc[3][1] += wv.w * a1; acc[3][2] += wv.w * a2; acc[3][3] += wv.w * a3;
        }
        __syncthreads();
    }
    #pragma unroll
    for (int j = 0; j < 4; j++) {
        int b = bg * 4 + j;
        *(float4*)(out + (size_t)s * sliceStride + (size_t)b * ldo + n0 + vq * 4) =
            make_float4(acc[0][j], acc[1][j], acc[2][j], acc[3][j]);
    }
}

// ---------------- fused per-step attention (+ previous step's gates) --------------
__global__ void attn_step_kernel(const float* __restrict__ Wa_w,
                                 const float* __restrict__ Wa_b,
                                 const float* __restrict__ Va_w,
                                 const float* __restrict__ Va_b,
                                 const float* __restrict__ enc,
                                 const float* __restrict__ b_hh,
                                 float* __restrict__ attn_out, int t)
{
    __shared__ __align__(16) float sh_h[HH];
    __shared__ __align__(16) float se[HH];
    __shared__ __align__(16) float sva[HH];
    __shared__ float ssc[SS];
    __shared__ float sms[2];
    const int b = blockIdx.x;
    const int tid = threadIdx.x;
    const int warp = tid >> 5, lane = tid & 31;

    if (t > 0) {
        const int j = tid;
        const float* p0 = g_part + (size_t)(0 * BB + b) * (3 * HH);
        const float* p1 = g_part + (size_t)(1 * BB + b) * (3 * HH);
        const float* p2 = g_part + (size_t)(2 * BB + b) * (3 * HH);
        const float* ge = g_gxe + ((size_t)(t - 1) * BB + b) * (3 * HH);
        float gx_r = ge[j] + p0[j] + p1[j];
        float gh_r = p2[j] + b_hh[j];
        float gx_z = ge[j + HH] + p0[j + HH] + p1[j + HH];
        float gh_z = p2[j + HH] + b_hh[j + HH];
        float gx_n = ge[j + 2 * HH] + p0[j + 2 * HH] + p1[j + 2 * HH];
        float gh_n = p2[j + 2 * HH] + b_hh[j + 2 * HH];
        float r = sig_f(gx_r + gh_r);
        float z = sig_f(gx_z + gh_z);
        float n = tanh_f(gx_n + r * gh_n);
        float hp = g_Hall[(size_t)(t - 1) * BB * HH + b * HH + j];
        float hn = (1.f - z) * n + z * hp;
        sh_h[j] = hn;
        g_Hall[(size_t)t * BB * HH + b * HH + j] = hn;
    } else {
        sh_h[tid] = g_Hall[b * HH + tid];
    }
    sva[tid] = Va_w[tid];
    __syncthreads();

    const float4* sh4 = (const float4*)sh_h;
    for (int rr = 0; rr < 32; rr++) {
        int i = warp * 32 + rr;
        const float4* wrow = (const float4*)(Wa_w + (size_t)i * HH);
        float sum = 0.f;
        #pragma unroll
        for (int it = 0; it < 4; it++) {
            int idx = lane + 32 * it;
            float4 w4 = wrow[idx];
            float4 h4 = sh4[idx];
            sum += w4.x * h4.x + w4.y * h4.y + w4.z * h4.z + w4.w * h4.w;
        }
        #pragma unroll
        for (int o = 16; o; o >>= 1) sum += __shfl_xor_sync(~0u, sum, o);
        if (lane == 0) se[i] = __expf(2.f * (sum + Wa_b[i]));
    }
    __syncthreads();

    const float4* se4 = (const float4*)se;
    const float4* sva4 = (const float4*)sva;
    for (int ss = 0; ss < 4; ss++) {
        int s = warp * 4 + ss;
        const float4* eu = (const float4*)(g_eu + (size_t)(b * SS + s) * HH);
        float sum = 0.f;
        #pragma unroll
        for (int it = 0; it < 4; it++) {
            int idx = lane + 32 * it;
            float4 e4 = eu[idx];
            float4 q4 = se4[idx];
            float4 v4 = sva4[idx];
            sum += v4.x * (1.f - 2.f * rcpf(q4.x * e4.x + 1.f));
            sum += v4.y * (1.f - 2.f * rcpf(q4.y * e4.y + 1.f));
            sum += v4.z * (1.f - 2.f * rcpf(q4.z * e4.z + 1.f));
            sum += v4.w * (1.f - 2.f * rcpf(q4.w * e4.w + 1.f));
        }
        #pragma unroll
        for (int o = 16; o; o >>= 1) sum += __shfl_xor_sync(~0u, sum, o);
        if (lane == 0) ssc[s] = sum + Va_b[0];
    }
    __syncthreads();

    if (tid == 0) {
        float m = ssc[0];
        for (int s = 1; s < SS; s++) m = fmaxf(m, ssc[s]);
        float sm = 0.f;
        for (int s = 0; s < SS; s++) sm += __expf(ssc[s] - m);
        sms[0] = m; sms[1] = rcpf(sm);
    }
    __syncthreads();
    if (tid < SS) {
        float w = __expf(ssc[tid] - sms[0]) * sms[1];
        ssc[tid] = w;
        attn_out[((size_t)b * TT + t) * SS + tid] = w;
    }
    __syncthreads();

    for (int kk = tid; kk < 2 * HH; kk += 512) {
        float a = 0.f;
        #pragma unroll 8
        for (int s = 0; s < SS; s++)
            a += ssc[s] * enc[(size_t)(b * SS + s) * (2 * HH) + kk];
        g_ctx[b * 2 * HH + kk] = a;
    }
}

__global__ void gates_kernel(const float* __restrict__ gxe_t,
                             const float* __restrict__ b_hh,
                             const float* __restrict__ h_old,
                             float* __restrict__ h_new,
                             float* __restrict__ h_new2)
{
    const int b = blockIdx.x;
    const int j = threadIdx.x;
    const float* p0 = g_part + (size_t)(0 * BB + b) * (3 * HH);
    const float* p1 = g_part + (size_t)(1 * BB + b) * (3 * HH);
    const float* p2 = g_part + (size_t)(2 * BB + b) * (3 * HH);
    const float* ge = gxe_t + (size_t)b * (3 * HH);
    float gx_r = ge[j] + p0[j] + p1[j];
    float gh_r = p2[j] + b_hh[j];
    float gx_z = ge[j + HH] + p0[j + HH] + p1[j + HH];
    float gh_z = p2[j + HH] + b_hh[j + HH];
    float gx_n = ge[j + 2 * HH] + p0[j + 2 * HH] + p1[j + 2 * HH];
    float gh_n = p2[j + 2 * HH] + b_hh[j + 2 * HH];
    float r = sig_f(gx_r + gh_r);
    float z = sig_f(gx_z + gh_z);
    float n = tanh_f(gx_n + r * gh_n);
    float hv = (1.f - z) * n + z * h_old[b * HH + j];
    h_new[b * HH + j] = hv;
    h_new2[b * HH + j] = hv;
}

__global__ void lsm_final_kernel(float* __restrict__ logp)
{
    const int r = blockIdx.x;
    __shared__ float sred[8];
    __shared__ float sls;
    const int tid = threadIdx.x;  // 256
    float s = 0.f;
    for (int i = tid; i < 1000; i += 256)
        s += g_psum[(size_t)r * 1024 + i];
    #pragma unroll
    for (int o = 16; o; o >>= 1) s += __shfl_down_sync(~0u, s, o);
    if ((tid & 31) == 0) sred[tid >> 5] = s;
    __syncthreads();
    if (tid == 0) {
        float tot = 0.f;
        for (int w = 0; w < 8; w++) tot += sred[w];
        sls = logf(tot);
    }
    __syncthreads();
    float ls = sls;
    float* row = logp + (size_t)r * VV;
    for (int i = tid * 4; i < VV; i += 1024) {
        float4 v = *(float4*)(row + i);
        v.x -= ls; v.y -= ls; v.z -= ls; v.w -= ls;
        *(float4*)(row + i) = v;
    }
}

// ---------------- launcher ---------------------------------------------------------
extern "C" void kernel_launch(void* const* d_in, const int* in_sizes, int n_in,
                              void* d_out, int out_size)
{
    const float* enc   = (const float*)d_in[0];
    const float* ehid  = (const float*)d_in[1];
    const int*   tgt   = (const int*)  d_in[2];
    const float* emb   = (const float*)d_in[3];
    const float* Wa_w  = (const float*)d_in[4];
    const float* Wa_b  = (const float*)d_in[5];
    const float* Ua_w  = (const float*)d_in[6];
    const float* Ua_b  = (const float*)d_in[7];
    const float* Va_w  = (const float*)d_in[8];
    const float* Va_b  = (const float*)d_in[9];
    const float* W_ih  = (const float*)d_in[10];
    const float* b_ih  = (const float*)d_in[11];
    const float* W_hh  = (const float*)d_in[12];
    const float* b_hh  = (const float*)d_in[13];
    const float* Wh    = (const float*)d_in[14];
    const float* bh    = (const float*)d_in[15];
    const float* out_w = (const float*)d_in[16];
    const float* out_b = (const float*)d_in[17];

    float* outp = (float*)d_out;
    float* logp = outp;
    float* hfin = outp + (size_t)BB * TT * VV;
    float* attn = hfin + (size_t)BB * HH;

    float *hall, *eu, *gxe, *ctx, *part, *psum;
    int* tokp;
    __nv_bfloat16 *hbf, *wbf;
    cudaGetSymbolAddress((void**)&hall, g_Hall);
    cudaGetSymbolAddress((void**)&eu,   g_eu);
    cudaGetSymbolAddress((void**)&gxe,  g_gxe);
    cudaGetSymbolAddress((void**)&ctx,  g_ctx);
    cudaGetSymbolAddress((void**)&part, g_part);
    cudaGetSymbolAddress((void**)&psum, g_psum);
    cudaGetSymbolAddress((void**)&tokp, g_tok);
    cudaGetSymbolAddress((void**)&hbf,  g_Hbf);
    cudaGetSymbolAddress((void**)&wbf,  g_Wbf);

    tok_kernel<<<4, 256>>>(tgt);
    gemm_tn_kernel<<<dim3(4, 1), 256>>>(ehid, 2 * HH, Wh, 2 * HH, hall, HH, bh, 2 * HH);
    big128_kernel<<<dim3(16, 4), 256>>>(enc, 2 * HH, nullptr, Ua_w, 2 * HH, Ua_b,
                                        2 * HH, eu, HH, 2);
    big128_kernel<<<dim3(8, 12), 256>>>(emb, HH, tokp, W_ih, 3 * HH, b_ih,
                                        HH, gxe, 3 * HH, 1);
    conv_bf16_kernel<<<4000, 256>>>(out_w, wbf, VV * HH / 4);

    for (int t = 0; t < TT; t++) {
        float* hcur = hall + (size_t)t * BB * HH;
        attn_step_kernel<<<BB, 512>>>(Wa_w, Wa_b, Va_w, Va_b, enc, b_hh, attn, t);
        pgemm_kernel<<<dim3(24, 3), 128>>>(ctx, 2 * HH, W_ih + HH, 3 * HH,
                                           hcur, HH, W_hh, HH,
                                           2, HH, part, 3 * HH, BB * 3 * HH);
    }
    gates_kernel<<<BB, 512>>>(gxe + (size_t)31 * BB * 3 * HH, b_hh,
                              hall + (size_t)31 * BB * HH,
                              hall + (size_t)32 * BB * HH, hfin);

    conv_bf16_kernel<<<512, 256>>>(hall + BB * HH, hbf, TT * BB * HH / 4);
    logits_hmma_kernel<<<dim3(8, 250), 256>>>(hbf, wbf, out_b, logp, psum);
    lsm_final_kernel<<<BB * TT, 256>>>(logp);
}

// round 7
// speedup vs baseline: 4.4877x; 1.0018x over previous
#include <cuda_runtime.h>
#include <cuda_bf16.h>
#include <math.h>
#include <stdint.h>

#define BB 32
#define SS 64
#define HH 512
#define TT 32
#define VV 32000
#define TILE_K 32

// ---------------- device scratch ------------------------------------------------
__device__ float g_Hall[(TT + 1) * BB * HH];
__device__ float g_eu[BB * SS * HH];
__device__ float g_gxe[TT * BB * 3 * HH];
__device__ float g_ctx[BB * 2 * HH];
__device__ float g_part[3 * BB * 3 * HH];
__device__ float g_psum[(size_t)BB * TT * 1024];
__device__ int   g_tok[TT * BB];
__device__ __nv_bfloat16 g_Hbf[TT * BB * HH];      // h_1..h_32 in bf16
__device__ __nv_bfloat16 g_Wbf[(size_t)VV * HH];   // out_w in bf16

typedef unsigned long long ull;
__device__ __forceinline__ void ffma2(ull& d, ull a, ull b) {
    asm("fma.rn.f32x2 %0, %1, %2, %0;" : "+l"(d) : "l"(a), "l"(b));
}
__device__ __forceinline__ ull dup2(float x) {
    ull r; asm("mov.b64 %0, {%1, %1};" : "=l"(r) : "f"(x)); return r;
}
__device__ __forceinline__ float2 unpack2(ull v) {
    float2 r; asm("mov.b64 {%0, %1}, %2;" : "=f"(r.x), "=f"(r.y) : "l"(v)); return r;
}
__device__ __forceinline__ float rcpf(float x) {
    float r; asm("rcp.approx.f32 %0, %1;" : "=f"(r) : "f"(x)); return r;
}
__device__ __forceinline__ float sig_f(float x) {
    x = fminf(fmaxf(x, -30.f), 30.f);
    return rcpf(1.f + __expf(-x));
}
__device__ __forceinline__ float tanh_f(float x) {
    x = fminf(fmaxf(x, -15.f), 15.f);
    float e = __expf(2.f * x);
    return 1.f - 2.f * rcpf(e + 1.f);
}
__device__ __forceinline__ uint32_t cvt_bf16x2(float hi, float lo) {
    uint32_t r;
    asm("cvt.rn.bf16x2.f32 %0, %1, %2;" : "=r"(r) : "f"(hi), "f"(lo));
    return r;
}

// mma.sync m16n8k16 bf16 -> f32 (plain PTX, supported on sm_80+; no arch-a feature)
__device__ __forceinline__ void mma16816(float* d, const uint32_t* a, const uint32_t* b) {
    asm volatile(
        "mma.sync.aligned.m16n8k16.row.col.f32.bf16.bf16.f32 "
        "{%0,%1,%2,%3}, {%4,%5,%6,%7}, {%8,%9}, {%0,%1,%2,%3};"
        : "+f"(d[0]), "+f"(d[1]), "+f"(d[2]), "+f"(d[3])
        : "r"(a[0]), "r"(a[1]), "r"(a[2]), "r"(a[3]), "r"(b[0]), "r"(b[1]));
}

// ---------------- bf16 converts ---------------------------------------------------
__global__ void conv_bf16_kernel(const float* __restrict__ src,
                                 __nv_bfloat16* __restrict__ dst, int n4)
{
    for (int i = blockIdx.x * blockDim.x + threadIdx.x; i < n4; i += gridDim.x * blockDim.x) {
        float4 v = *(const float4*)(src + (size_t)i * 4);
        uint2 o;
        o.x = cvt_bf16x2(v.y, v.x);
        o.y = cvt_bf16x2(v.w, v.z);
        *(uint2*)(dst + (size_t)i * 4) = o;
    }
}

// ---------------- tokens ----------------------------------------------------------
__global__ void tok_kernel(const int* __restrict__ tgt) {
    int i = blockIdx.x * 256 + threadIdx.x;
    if (i < TT * BB) {
        int t = i >> 5, b = i & 31;
        g_tok[i] = (t == 0) ? 0 : tgt[b * TT + t - 1];
    }
}

// ---------------- logits: bf16 HMMA GEMM + fused exp psum -------------------------
// D[1024,32000] = H[1024,512] @ W[32000,512]^T + bias.
// grid (8 m-tiles, 250 n-tiles), block 256 (8 warps: 2 M x 4 N, warp tile 64x32).
#define SPAD 40   // smem row stride in bf16 elems (80 B) -> conflict-free quads
__global__ __launch_bounds__(256)
void logits_hmma_kernel(const __nv_bfloat16* __restrict__ Hbf,
                        const __nv_bfloat16* __restrict__ Wbf,
                        const float* __restrict__ out_b,
                        float* __restrict__ logp, float* __restrict__ psum)
{
    __shared__ __align__(16) __nv_bfloat16 sA[128 * SPAD];
    __shared__ __align__(16) __nv_bfloat16 sB[128 * SPAD];
    __shared__ float sbias[128];
    const int tid = threadIdx.x;
    const int wid = tid >> 5, lane = tid & 31;
    const int m0 = blockIdx.x * 128;
    const int n0 = blockIdx.y * 128;
    if (tid < 128) sbias[tid] = out_b[n0 + tid];

    // global loaders: 2 x 16B per thread per matrix per k-tile
    const int lrow = tid >> 2;        // 0..63
    const int lc = tid & 3;           // 16B chunk within 64B k-slab
    const __nv_bfloat16* Ag0 = Hbf + (size_t)(m0 + lrow) * HH + lc * 8;
    const __nv_bfloat16* Ag1 = Ag0 + (size_t)64 * HH;
    const __nv_bfloat16* Bg0 = Wbf + (size_t)(n0 + lrow) * HH + lc * 8;
    const __nv_bfloat16* Bg1 = Bg0 + (size_t)64 * HH;
    __nv_bfloat16* sA0 = sA + lrow * SPAD + lc * 8;
    __nv_bfloat16* sA1 = sA0 + 64 * SPAD;
    __nv_bfloat16* sB0 = sB + lrow * SPAD + lc * 8;
    __nv_bfloat16* sB1 = sB0 + 64 * SPAD;

    uint4 ra0 = *(const uint4*)Ag0;
    uint4 ra1 = *(const uint4*)Ag1;
    uint4 rb0 = *(const uint4*)Bg0;
    uint4 rb1 = *(const uint4*)Bg1;

    // compute-side bases
    const int mw = (wid >> 2) * 64, nw = (wid & 3) * 32;
    const int qr = lane >> 2, qc = lane & 3;
    const __nv_bfloat16* pa = sA + (mw + qr) * SPAD + qc * 2;
    const __nv_bfloat16* pb = sB + (nw + qr) * SPAD + qc * 2;

    float acc[4][4][4];
    #pragma unroll
    for (int i = 0; i < 4; i++)
        #pragma unroll
        for (int j = 0; j < 4; j++)
            #pragma unroll
            for (int e = 0; e < 4; e++) acc[i][j][e] = 0.f;

    #pragma unroll 1
    for (int kt = 0; kt < 16; kt++) {
        *(uint4*)sA0 = ra0; *(uint4*)sA1 = ra1;
        *(uint4*)sB0 = rb0; *(uint4*)sB1 = rb1;
        __syncthreads();
        if (kt < 15) {
            ra0 = *(const uint4*)(Ag0 + (kt + 1) * 32);
            ra1 = *(const uint4*)(Ag1 + (kt + 1) * 32);
            rb0 = *(const uint4*)(Bg0 + (kt + 1) * 32);
            rb1 = *(const uint4*)(Bg1 + (kt + 1) * 32);
        }
        #pragma unroll
        for (int ks = 0; ks < 2; ks++) {
            uint32_t af[4][4], bf[4][2];
            #pragma unroll
            for (int mi = 0; mi < 4; mi++) {
                const __nv_bfloat16* p = pa + mi * 16 * SPAD + ks * 16;
                af[mi][0] = *(const uint32_t*)(p);
                af[mi][1] = *(const uint32_t*)(p + 8 * SPAD);
                af[mi][2] = *(const uint32_t*)(p + 8);
                af[mi][3] = *(const uint32_t*)(p + 8 * SPAD + 8);
            }
            #pragma unroll
            for (int ni = 0; ni < 4; ni++) {
                const __nv_bfloat16* p = pb + ni * 8 * SPAD + ks * 16;
                bf[ni][0] = *(const uint32_t*)(p);
                bf[ni][1] = *(const uint32_t*)(p + 8);
            }
            #pragma unroll
            for (int mi = 0; mi < 4; mi++)
                #pragma unroll
                for (int ni = 0; ni < 4; ni++)
                    mma16816(acc[mi][ni], af[mi], bf[ni]);
        }
        __syncthreads();
    }

    // epilogue: bias + store (permuted rows) + exp row-partials
    float es[8];
    #pragma unroll
    for (int i = 0; i < 8; i++) es[i] = 0.f;

    #pragma unroll
    for (int mi = 0; mi < 4; mi++) {
        const int rA = m0 + mw + mi * 16 + qr;        // global m of c0,c1
        const int rB = rA + 8;                        // global m of c2,c3
        const int tqA = rA >> 5, bqA = rA & 31;
        const int tqB = rB >> 5, bqB = rB & 31;
        float* cpA = logp + (size_t)(bqA * TT + tqA) * VV + n0;
        float* cpB = logp + (size_t)(bqB * TT + tqB) * VV + n0;
        #pragma unroll
        for (int ni = 0; ni < 4; ni++) {
            const int cl = nw + ni * 8 + qc * 2;      // local col in [0,128)
            float v0 = acc[mi][ni][0] + sbias[cl];
            float v1 = acc[mi][ni][1] + sbias[cl + 1];
            float v2 = acc[mi][ni][2] + sbias[cl];
            float v3 = acc[mi][ni][3] + sbias[cl + 1];
            *(float2*)(cpA + cl) = make_float2(v0, v1);
            *(float2*)(cpB + cl) = make_float2(v2, v3);
            es[mi * 2 + 0] += __expf(v0) + __expf(v1);
            es[mi * 2 + 1] += __expf(v2) + __expf(v3);
        }
    }
    // quad reduce (lanes sharing qr): xor over the two low lane bits
    #pragma unroll
    for (int i = 0; i < 8; i++) {
        es[i] += __shfl_xor_sync(0xffffffffu, es[i], 1);
        es[i] += __shfl_xor_sync(0xffffffffu, es[i], 2);
    }
    if (qc == 0) {
        const int col = blockIdx.y * 4 + (wid & 3);
        #pragma unroll
        for (int mi = 0; mi < 4; mi++) {
            int rA = m0 + mw + mi * 16 + qr;
            int rB = rA + 8;
            int rowA = (rA & 31) * TT + (rA >> 5);
            int rowB = (rB & 31) * TT + (rB >> 5);
            psum[(size_t)rowA * 1024 + col] = es[mi * 2 + 0];
            psum[(size_t)rowB * 1024 + col] = es[mi * 2 + 1];
        }
    }
}

// ---------------- fp32 big GEMM (e2u / gxe), register double-buffered -------------
__global__ __launch_bounds__(256, 2)
void big128_kernel(const float* __restrict__ A, int lda,
                   const int* __restrict__ tokens,
                   const float* __restrict__ W, int ldw,
                   const float* __restrict__ bias, int K,
                   float* __restrict__ C, int ldc, int mode)
{
    __shared__ __align__(16) float sA[16][132];
    __shared__ __align__(16) float sB[16][132];
    const int tid = threadIdx.x;
    const int m0 = blockIdx.x * 128;
    const int n0 = blockIdx.y * 128;
    const int tx4 = (tid & 15) * 4;
    const int ty4 = (tid >> 4) * 4;

    const int row0 = tid >> 2,         kq0 = (tid & 3) * 4;
    const int row1 = (tid + 256) >> 2;
    long ar0 = tokens ? (long)tokens[m0 + row0] : (long)(m0 + row0);
    long ar1 = tokens ? (long)tokens[m0 + row1] : (long)(m0 + row1);
    const float* ap0 = A + ar0 * lda + kq0;
    const float* ap1 = A + ar1 * lda + kq0;
    const float* wp0 = W + (size_t)(n0 + row0) * ldw + kq0;
    const float* wp1 = W + (size_t)(n0 + row1) * ldw + kq0;

    float4 ra0 = *(const float4*)ap0;
    float4 ra1 = *(const float4*)ap1;
    float4 rw0 = *(const float4*)wp0;
    float4 rw1 = *(const float4*)wp1;

    ull acc[4][8];
    #pragma unroll
    for (int i = 0; i < 4; i++)
        #pragma unroll
        for (int j = 0; j < 8; j++) acc[i][j] = 0ull;

    const int kTiles = K / 16;
    for (int kt = 0; kt < kTiles; kt++) {
        sA[kq0 + 0][row0] = ra0.x; sA[kq0 + 1][row0] = ra0.y;
        sA[kq0 + 2][row0] = ra0.z; sA[kq0 + 3][row0] = ra0.w;
        sA[kq0 + 0][row1] = ra1.x; sA[kq0 + 1][row1] = ra1.y;
        sA[kq0 + 2][row1] = ra1.z; sA[kq0 + 3][row1] = ra1.w;
        sB[kq0 + 0][row0] = rw0.x; sB[kq0 + 1][row0] = rw0.y;
        sB[kq0 + 2][row0] = rw0.z; sB[kq0 + 3][row0] = rw0.w;
        sB[kq0 + 0][row1] = rw1.x; sB[kq0 + 1][row1] = rw1.y;
        sB[kq0 + 2][row1] = rw1.z; sB[kq0 + 3][row1] = rw1.w;
        __syncthreads();
        if (kt + 1 < kTiles) {
            int ko = (kt + 1) * 16;
            ra0 = *(const float4*)(ap0 + ko);
            ra1 = *(const float4*)(ap1 + ko);
            rw0 = *(const float4*)(wp0 + ko);
            rw1 = *(const float4*)(wp1 + ko);
        }
        #pragma unroll
        for (int k = 0; k < 16; k++) {
            ulonglong2 a0 = *(const ulonglong2*)&sA[k][ty4];
            ulonglong2 a1 = *(const ulonglong2*)&sA[k][64 + ty4];
            float4 b0 = *(const float4*)&sB[k][tx4];
            float4 b1 = *(const float4*)&sB[k][64 + tx4];
            ull ap[4] = {a0.x, a0.y, a1.x, a1.y};
            ull bd[8] = {dup2(b0.x), dup2(b0.y), dup2(b0.z), dup2(b0.w),
                         dup2(b1.x), dup2(b1.y), dup2(b1.z), dup2(b1.w)};
            #pragma unroll
            for (int mp = 0; mp < 4; mp++)
                #pragma unroll
                for (int n = 0; n < 8; n++)
                    ffma2(acc[mp][n], ap[mp], bd[n]);
        }
        __syncthreads();
    }

    float4 bs0 = *(const float4*)&bias[n0 + tx4];
    float4 bs1 = *(const float4*)&bias[n0 + 64 + tx4];
    #pragma unroll
    for (int mp = 0; mp < 4; mp++) {
        #pragma unroll
        for (int half = 0; half < 2; half++) {
            int gm = m0 + (mp >> 1) * 64 + ty4 + (mp & 1) * 2 + half;
            float v[8];
            #pragma unroll
            for (int n = 0; n < 8; n++) {
                float2 p = unpack2(acc[mp][n]);
                v[n] = half ? p.y : p.x;
            }
            v[0] += bs0.x; v[1] += bs0.y; v[2] += bs0.z; v[3] += bs0.w;
            v[4] += bs1.x; v[5] += bs1.y; v[6] += bs1.z; v[7] += bs1.w;
            if (mode == 2) {
                #pragma unroll
                for (int n = 0; n < 8; n++) v[n] = __expf(2.f * v[n]);
            }
            float* cp = C + (size_t)gm * ldc + n0;
            *(float4*)(cp + tx4)      = make_float4(v[0], v[1], v[2], v[3]);
            *(float4*)(cp + 64 + tx4) = make_float4(v[4], v[5], v[6], v[7]);
        }
    }
}

// ---------------- small gemm (h0 only) --------------------------------------------
__global__ void gemm_tn_kernel(const float* __restrict__ A, int lda,
                               const float* __restrict__ W, int ldb,
                               float* __restrict__ C, int ldc,
                               const float* __restrict__ bias, int K)
{
    __shared__ float sa[TILE_K][33];
    __shared__ float sb[TILE_K][132];
    const int tid = threadIdx.x;
    const int n0 = blockIdx.x * 128;
    const int vq = tid & 31, bg = tid >> 5;
    const int lm = tid >> 3, lk = (tid & 7) * 4;
    float acc[4][4] = {};
    for (int k0 = 0; k0 < K; k0 += TILE_K) {
        float4 a4 = *(const float4*)(A + (size_t)lm * lda + k0 + lk);
        sa[lk + 0][lm] = a4.x; sa[lk + 1][lm] = a4.y;
        sa[lk + 2][lm] = a4.z; sa[lk + 3][lm] = a4.w;
        #pragma unroll
        for (int it = 0; it < 4; it++) {
            int n = lm + 32 * it;
            float4 b4 = *(const float4*)(W + (size_t)(n0 + n) * ldb + k0 + lk);
            sb[lk + 0][n] = b4.x; sb[lk + 1][n] = b4.y;
            sb[lk + 2][n] = b4.z; sb[lk + 3][n] = b4.w;
        }
        __syncthreads();
        #pragma unroll 8
        for (int k = 0; k < TILE_K; k++) {
            float4 bv = *(const float4*)(&sb[k][vq * 4]);
            float a0 = sa[k][bg * 4 + 0], a1 = sa[k][bg * 4 + 1];
            float a2 = sa[k][bg * 4 + 2], a3 = sa[k][bg * 4 + 3];
            acc[0][0] += bv.x * a0; acc[0][1] += bv.x * a1; acc[0][2] += bv.x * a2; acc[0][3] += bv.x * a3;
            acc[1][0] += bv.y * a0; acc[1][1] += bv.y * a1; acc[1][2] += bv.y * a2; acc[1][3] += bv.y * a3;
            acc[2][0] += bv.z * a0; acc[2][1] += bv.z * a1; acc[2][2] += bv.z * a2; acc[2][3] += bv.z * a3;
            acc[3][0] += bv.w * a0; acc[3][1] += bv.w * a1; acc[3][2] += bv.w * a2; acc[3][3] += bv.w * a3;
        }
        __syncthreads();
    }
    float4 bs4 = *(const float4*)(bias + n0 + vq * 4);
    #pragma unroll
    for (int j = 0; j < 4; j++) {
        float4 o;
        o.x = acc[0][j] + bs4.x; o.y = acc[1][j] + bs4.y;
        o.z = acc[2][j] + bs4.z; o.w = acc[3][j] + bs4.w;
        *(float4*)(C + (size_t)(bg * 4 + j) * ldc + n0 + vq * 4) = o;
    }
}

// ---------------- split-K partial GEMM (loop GRU) ----------------------------------
__global__ void pgemm_kernel(const float* __restrict__ A1, int lda1,
                             const float* __restrict__ W1, int ldw1,
                             const float* __restrict__ A2, int lda2,
                             const float* __restrict__ W2, int ldw2,
                             int slices1, int kPerSlice,
                             float* __restrict__ out, int ldo, int sliceStride)
{
    __shared__ float sxh[TILE_K][33];
    __shared__ float sw[TILE_K][68];
    const int tid = threadIdx.x;
    const int s = blockIdx.y;
    const int n0 = blockIdx.x * 64;
    const float* a; int la; const float* w; int lw;
    if (s < slices1) { a = A1 + s * kPerSlice; la = lda1; w = W1 + s * kPerSlice; lw = ldw1; }
    else { a = A2; la = lda2; w = W2; lw = ldw2; }
    const int kTiles = kPerSlice / TILE_K;
    const int lb = tid >> 2, lk = (tid & 3) * 4;
    const int ln = tid >> 3, lk8 = (tid & 7) * 4;
    const int vq = tid & 15, bg = tid >> 4;

    float4 ra[2], rw[4];
    #pragma unroll
    for (int it = 0; it < 2; it++)
        ra[it] = *(const float4*)(a + (size_t)lb * la + lk + 16 * it);
    #pragma unroll
    for (int it = 0; it < 4; it++)
        rw[it] = *(const float4*)(w + (size_t)(n0 + ln + 16 * it) * lw + lk8);

    float acc[4][4] = {};
    for (int kt = 0; kt < kTiles; kt++) {
        #pragma unroll
        for (int it = 0; it < 2; it++) {
            int kk = lk + 16 * it;
            sxh[kk + 0][lb] = ra[it].x; sxh[kk + 1][lb] = ra[it].y;
            sxh[kk + 2][lb] = ra[it].z; sxh[kk + 3][lb] = ra[it].w;
        }
        #pragma unroll
        for (int it = 0; it < 4; it++) {
            int n = ln + 16 * it;
            sw[lk8 + 0][n] = rw[it].x; sw[lk8 + 1][n] = rw[it].y;
            sw[lk8 + 2][n] = rw[it].z; sw[lk8 + 3][n] = rw[it].w;
        }
        __syncthreads();
        if (kt + 1 < kTiles) {
            int ko = (kt + 1) * TILE_K;
            #pragma unroll
            for (int it = 0; it < 2; it++)
                ra[it] = *(const float4*)(a + (size_t)lb * la + ko + lk + 16 * it);
            #pragma unroll
            for (int it = 0; it < 4; it++)
                rw[it] = *(const float4*)(w + (size_t)(n0 + ln + 16 * it) * lw + ko + lk8);
        }
        #pragma unroll 8
        for (int k = 0; k < TILE_K; k++) {
            float4 wv = *(const float4*)(&sw[k][vq * 4]);
            float a0 = sxh[k][bg * 4 + 0], a1 = sxh[k][bg * 4 + 1];
            float a2 = sxh[k][bg * 4 + 2], a3 = sxh[k][bg * 4 + 3];
            acc[0][0] += wv.x * a0; acc[0][1] += wv.x * a1; acc[0][2] += wv.x * a2; acc[0][3] += wv.x * a3;
            acc[1][0] += wv.y * a0; acc[1][1] += wv.y * a1; acc[1][2] += wv.y * a2; acc[1][3] += wv.y * a3;
            acc[2][0] += wv.z * a0; acc[2][1] += wv.z * a1; acc[2][2] += wv.z * a2; acc[2][3] += wv.z * a3;
            acc[3][0] += wv.w * a0; acc[3][1] += wv.w * a1; acc[3][2] += wv.w * a2; acc[3][3] += wv.w * a3;
        }
        __syncthreads();
    }
    #pragma unroll
    for (int j = 0; j < 4; j++) {
        int b = bg * 4 + j;
        *(float4*)(out + (size_t)s * sliceStride + (size_t)b * ldo + n0 + vq * 4) =
            make_float4(acc[0][j], acc[1][j], acc[2][j], acc[3][j]);
    }
}

// ---------------- fused per-step attention (+ previous step's gates) --------------
__global__ void attn_step_kernel(const float* __restrict__ Wa_w,
                                 const float* __restrict__ Wa_b,
                                 const float* __restrict__ Va_w,
                                 const float* __restrict__ Va_b,
                                 const float* __restrict__ enc,
                                 const float* __restrict__ b_hh,
                                 float* __restrict__ attn_out, int t)
{
    __shared__ __align__(16) float sh_h[HH];
    __shared__ __align__(16) float se[HH];
    __shared__ __align__(16) float sva[HH];
    __shared__ float ssc[SS];
    __shared__ float sms[2];
    const int b = blockIdx.x;
    const int tid = threadIdx.x;
    const int warp = tid >> 5, lane = tid & 31;

    if (t > 0) {
        const int j = tid;
        const float* p0 = g_part + (size_t)(0 * BB + b) * (3 * HH);
        const float* p1 = g_part + (size_t)(1 * BB + b) * (3 * HH);
        const float* p2 = g_part + (size_t)(2 * BB + b) * (3 * HH);
        const float* ge = g_gxe + ((size_t)(t - 1) * BB + b) * (3 * HH);
        float gx_r = ge[j] + p0[j] + p1[j];
        float gh_r = p2[j] + b_hh[j];
        float gx_z = ge[j + HH] + p0[j + HH] + p1[j + HH];
        float gh_z = p2[j + HH] + b_hh[j + HH];
        float gx_n = ge[j + 2 * HH] + p0[j + 2 * HH] + p1[j + 2 * HH];
        float gh_n = p2[j + 2 * HH] + b_hh[j + 2 * HH];
        float r = sig_f(gx_r + gh_r);
        float z = sig_f(gx_z + gh_z);
        float n = tanh_f(gx_n + r * gh_n);
        float hp = g_Hall[(size_t)(t - 1) * BB * HH + b * HH + j];
        float hn = (1.f - z) * n + z * hp;
        sh_h[j] = hn;
        g_Hall[(size_t)t * BB * HH + b * HH + j] = hn;
    } else {
        sh_h[tid] = g_Hall[b * HH + tid];
    }
    sva[tid] = Va_w[tid];
    __syncthreads();

    const float4* sh4 = (const float4*)sh_h;
    for (int rr = 0; rr < 32; rr++) {
        int i = warp * 32 + rr;
        const float4* wrow = (const float4*)(Wa_w + (size_t)i * HH);
        float sum = 0.f;
        #pragma unroll
        for (int it = 0; it < 4; it++) {
            int idx = lane + 32 * it;
            float4 w4 = wrow[idx];
            float4 h4 = sh4[idx];
            sum += w4.x * h4.x + w4.y * h4.y + w4.z * h4.z + w4.w * h4.w;
        }
        #pragma unroll
        for (int o = 16; o; o >>= 1) sum += __shfl_xor_sync(~0u, sum, o);
        if (lane == 0) se[i] = __expf(2.f * (sum + Wa_b[i]));
    }
    __syncthreads();

    const float4* se4 = (const float4*)se;
    const float4* sva4 = (const float4*)sva;
    for (int ss = 0; ss < 4; ss++) {
        int s = warp * 4 + ss;
        const float4* eu = (const float4*)(g_eu + (size_t)(b * SS + s) * HH);
        float sum = 0.f;
        #pragma unroll
        for (int it = 0; it < 4; it++) {
            int idx = lane + 32 * it;
            float4 e4 = eu[idx];
            float4 q4 = se4[idx];
            float4 v4 = sva4[idx];
            sum += v4.x * (1.f - 2.f * rcpf(q4.x * e4.x + 1.f));
            sum += v4.y * (1.f - 2.f * rcpf(q4.y * e4.y + 1.f));
            sum += v4.z * (1.f - 2.f * rcpf(q4.z * e4.z + 1.f));
            sum += v4.w * (1.f - 2.f * rcpf(q4.w * e4.w + 1.f));
        }
        #pragma unroll
        for (int o = 16; o; o >>= 1) sum += __shfl_xor_sync(~0u, sum, o);
        if (lane == 0) ssc[s] = sum + Va_b[0];
    }
    __syncthreads();

    if (tid == 0) {
        float m = ssc[0];
        for (int s = 1; s < SS; s++) m = fmaxf(m, ssc[s]);
        float sm = 0.f;
        for (int s = 0; s < SS; s++) sm += __expf(ssc[s] - m);
        sms[0] = m; sms[1] = rcpf(sm);
    }
    __syncthreads();
    if (tid < SS) {
        float w = __expf(ssc[tid] - sms[0]) * sms[1];
        ssc[tid] = w;
        attn_out[((size_t)b * TT + t) * SS + tid] = w;
    }
    __syncthreads();

    for (int kk = tid; kk < 2 * HH; kk += 512) {
        float a = 0.f;
        #pragma unroll 8
        for (int s = 0; s < SS; s++)
            a += ssc[s] * enc[(size_t)(b * SS + s) * (2 * HH) + kk];
        g_ctx[b * 2 * HH + kk] = a;
    }
}

__global__ void gates_kernel(const float* __restrict__ gxe_t,
                             const float* __restrict__ b_hh,
                             const float* __restrict__ h_old,
                             float* __restrict__ h_new,
                             float* __restrict__ h_new2)
{
    const int b = blockIdx.x;
    const int j = threadIdx.x;
    const float* p0 = g_part + (size_t)(0 * BB + b) * (3 * HH);
    const float* p1 = g_part + (size_t)(1 * BB + b) * (3 * HH);
    const float* p2 = g_part + (size_t)(2 * BB + b) * (3 * HH);
    const float* ge = gxe_t + (size_t)b * (3 * HH);
    float gx_r = ge[j] + p0[j] + p1[j];
    float gh_r = p2[j] + b_hh[j];
    float gx_z = ge[j + HH] + p0[j + HH] + p1[j + HH];
    float gh_z = p2[j + HH] + b_hh[j + HH];
    float gx_n = ge[j + 2 * HH] + p0[j + 2 * HH] + p1[j + 2 * HH];
    float gh_n = p2[j + 2 * HH] + b_hh[j + 2 * HH];
    float r = sig_f(gx_r + gh_r);
    float z = sig_f(gx_z + gh_z);
    float n = tanh_f(gx_n + r * gh_n);
    float hv = (1.f - z) * n + z * h_old[b * HH + j];
    h_new[b * HH + j] = hv;
    h_new2[b * HH + j] = hv;
}

__global__ void lsm_final_kernel(float* __restrict__ logp)
{
    const int r = blockIdx.x;
    __shared__ float sred[8];
    __shared__ float sls;
    const int tid = threadIdx.x;  // 256
    float s = 0.f;
    for (int i = tid; i < 1000; i += 256)
        s += g_psum[(size_t)r * 1024 + i];
    #pragma unroll
    for (int o = 16; o; o >>= 1) s += __shfl_down_sync(~0u, s, o);
    if ((tid & 31) == 0) sred[tid >> 5] = s;
    __syncthreads();
    if (tid == 0) {
        float tot = 0.f;
        for (int w = 0; w < 8; w++) tot += sred[w];
        sls = logf(tot);
    }
    __syncthreads();
    float ls = sls;
    float* row = logp + (size_t)r * VV;
    for (int i = tid * 4; i < VV; i += 1024) {
        float4 v = *(float4*)(row + i);
        v.x -= ls; v.y -= ls; v.z -= ls; v.w -= ls;
        *(float4*)(row + i) = v;
    }
}

// ---------------- launcher ---------------------------------------------------------
extern "C" void kernel_launch(void* const* d_in, const int* in_sizes, int n_in,
                              void* d_out, int out_size)
{
    const float* enc   = (const float*)d_in[0];
    const float* ehid  = (const float*)d_in[1];
    const int*   tgt   = (const int*)  d_in[2];
    const float* emb   = (const float*)d_in[3];
    const float* Wa_w  = (const float*)d_in[4];
    const float* Wa_b  = (const float*)d_in[5];
    const float* Ua_w  = (const float*)d_in[6];
    const float* Ua_b  = (const float*)d_in[7];
    const float* Va_w  = (const float*)d_in[8];
    const float* Va_b  = (const float*)d_in[9];
    const float* W_ih  = (const float*)d_in[10];
    const float* b_ih  = (const float*)d_in[11];
    const float* W_hh  = (const float*)d_in[12];
    const float* b_hh  = (const float*)d_in[13];
    const float* Wh    = (const float*)d_in[14];
    const float* bh    = (const float*)d_in[15];
    const float* out_w = (const float*)d_in[16];
    const float* out_b = (const float*)d_in[17];

    float* outp = (float*)d_out;
    float* logp = outp;
    float* hfin = outp + (size_t)BB * TT * VV;
    float* attn = hfin + (size_t)BB * HH;

    float *hall, *eu, *gxe, *ctx, *part, *psum;
    int* tokp;
    __nv_bfloat16 *hbf, *wbf;
    cudaGetSymbolAddress((void**)&hall, g_Hall);
    cudaGetSymbolAddress((void**)&eu,   g_eu);
    cudaGetSymbolAddress((void**)&gxe,  g_gxe);
    cudaGetSymbolAddress((void**)&ctx,  g_ctx);
    cudaGetSymbolAddress((void**)&part, g_part);
    cudaGetSymbolAddress((void**)&psum, g_psum);
    cudaGetSymbolAddress((void**)&tokp, g_tok);
    cudaGetSymbolAddress((void**)&hbf,  g_Hbf);
    cudaGetSymbolAddress((void**)&wbf,  g_Wbf);

    tok_kernel<<<4, 256>>>(tgt);
    gemm_tn_kernel<<<dim3(4, 1), 256>>>(ehid, 2 * HH, Wh, 2 * HH, hall, HH, bh, 2 * HH);
    big128_kernel<<<dim3(16, 4), 256>>>(enc, 2 * HH, nullptr, Ua_w, 2 * HH, Ua_b,
                                        2 * HH, eu, HH, 2);
    big128_kernel<<<dim3(8, 12), 256>>>(emb, HH, tokp, W_ih, 3 * HH, b_ih,
                                        HH, gxe, 3 * HH, 1);
    conv_bf16_kernel<<<4000, 256>>>(out_w, wbf, VV * HH / 4);

    for (int t = 0; t < TT; t++) {
        float* hcur = hall + (size_t)t * BB * HH;
        attn_step_kernel<<<BB, 512>>>(Wa_w, Wa_b, Va_w, Va_b, enc, b_hh, attn, t);
        pgemm_kernel<<<dim3(24, 3), 128>>>(ctx, 2 * HH, W_ih + HH, 3 * HH,
                                           hcur, HH, W_hh, HH,
                                           2, HH, part, 3 * HH, BB * 3 * HH);
    }
    gates_kernel<<<BB, 512>>>(gxe + (size_t)31 * BB * 3 * HH, b_hh,
                              hall + (size_t)31 * BB * HH,
                              hall + (size_t)32 * BB * HH, hfin);

    conv_bf16_kernel<<<512, 256>>>(hall + BB * HH, hbf, TT * BB * HH / 4);
    logits_hmma_kernel<<<dim3(8, 250), 256>>>(hbf, wbf, out_b, logp, psum);
    lsm_final_kernel<<<BB * TT, 256>>>(logp);
}

// round 8
// speedup vs baseline: 4.5448x; 1.0127x over previous
#include <cuda_runtime.h>
#include <cuda_bf16.h>
#include <math.h>
#include <stdint.h>

#define BB 32
#define SS 64
#define HH 512
#define TT 32
#define VV 32000
#define TILE_K 32

// ---------------- device scratch ------------------------------------------------
__device__ float g_Hall[(TT + 1) * BB * HH];
__device__ float g_eu[BB * SS * HH];
__device__ float g_gxe[TT * BB * 3 * HH];
__device__ float g_ctx[BB * 2 * HH];
__device__ float g_part[3 * BB * 3 * HH];
__device__ float g_psum[(size_t)BB * TT * 1024];
__device__ int   g_tok[TT * BB];
__device__ __nv_bfloat16 g_Hbf[TT * BB * HH];      // h_1..h_32 in bf16
__device__ __nv_bfloat16 g_Wbf[(size_t)VV * HH];   // out_w in bf16

typedef unsigned long long ull;
__device__ __forceinline__ void ffma2(ull& d, ull a, ull b) {
    asm("fma.rn.f32x2 %0, %1, %2, %0;" : "+l"(d) : "l"(a), "l"(b));
}
__device__ __forceinline__ ull dup2(float x) {
    ull r; asm("mov.b64 %0, {%1, %1};" : "=l"(r) : "f"(x)); return r;
}
__device__ __forceinline__ float2 unpack2(ull v) {
    float2 r; asm("mov.b64 {%0, %1}, %2;" : "=f"(r.x), "=f"(r.y) : "l"(v)); return r;
}
__device__ __forceinline__ float rcpf(float x) {
    float r; asm("rcp.approx.f32 %0, %1;" : "=f"(r) : "f"(x)); return r;
}
__device__ __forceinline__ float sig_f(float x) {
    x = fminf(fmaxf(x, -30.f), 30.f);
    return rcpf(1.f + __expf(-x));
}
__device__ __forceinline__ float tanh_f(float x) {
    x = fminf(fmaxf(x, -15.f), 15.f);
    float e = __expf(2.f * x);
    return 1.f - 2.f * rcpf(e + 1.f);
}
__device__ __forceinline__ uint32_t cvt_bf16x2(float hi, float lo) {
    uint32_t r;
    asm("cvt.rn.bf16x2.f32 %0, %1, %2;" : "=r"(r) : "f"(hi), "f"(lo));
    return r;
}

// mma.sync m16n8k16 bf16 -> f32 (plain PTX, supported on sm_80+; no arch-a feature)
__device__ __forceinline__ void mma16816(float* d, const uint32_t* a, const uint32_t* b) {
    asm volatile(
        "mma.sync.aligned.m16n8k16.row.col.f32.bf16.bf16.f32 "
        "{%0,%1,%2,%3}, {%4,%5,%6,%7}, {%8,%9}, {%0,%1,%2,%3};"
        : "+f"(d[0]), "+f"(d[1]), "+f"(d[2]), "+f"(d[3])
        : "r"(a[0]), "r"(a[1]), "r"(a[2]), "r"(a[3]), "r"(b[0]), "r"(b[1]));
}

// ---------------- bf16 converts ---------------------------------------------------
__global__ void conv_bf16_kernel(const float* __restrict__ src,
                                 __nv_bfloat16* __restrict__ dst, int n4)
{
    for (int i = blockIdx.x * blockDim.x + threadIdx.x; i < n4; i += gridDim.x * blockDim.x) {
        float4 v = *(const float4*)(src + (size_t)i * 4);
        uint2 o;
        o.x = cvt_bf16x2(v.y, v.x);
        o.y = cvt_bf16x2(v.w, v.z);
        *(uint2*)(dst + (size_t)i * 4) = o;
    }
}

// ---------------- tokens ----------------------------------------------------------
__global__ void tok_kernel(const int* __restrict__ tgt) {
    int i = blockIdx.x * 256 + threadIdx.x;
    if (i < TT * BB) {
        int t = i >> 5, b = i & 31;
        g_tok[i] = (t == 0) ? 0 : tgt[b * TT + t - 1];
    }
}

// ---------------- logits: bf16 HMMA GEMM + fused exp psum -------------------------
// D[1024,32000] = H[1024,512] @ W[32000,512]^T + bias.
// grid (8 m-tiles, 250 n-tiles), block 256 (8 warps: 2 M x 4 N, warp tile 64x32).
#define SPAD 40   // smem row stride in bf16 elems (80 B) -> conflict-free quads
__global__ __launch_bounds__(256)
void logits_hmma_kernel(const __nv_bfloat16* __restrict__ Hbf,
                        const __nv_bfloat16* __restrict__ Wbf,
                        const float* __restrict__ out_b,
                        float* __restrict__ logp, float* __restrict__ psum)
{
    __shared__ __align__(16) __nv_bfloat16 sA[128 * SPAD];
    __shared__ __align__(16) __nv_bfloat16 sB[128 * SPAD];
    __shared__ float sbias[128];
    const int tid = threadIdx.x;
    const int wid = tid >> 5, lane = tid & 31;
    const int m0 = blockIdx.x * 128;
    const int n0 = blockIdx.y * 128;
    if (tid < 128) sbias[tid] = out_b[n0 + tid];

    // global loaders: 2 x 16B per thread per matrix per k-tile
    const int lrow = tid >> 2;        // 0..63
    const int lc = tid & 3;           // 16B chunk within 64B k-slab
    const __nv_bfloat16* Ag0 = Hbf + (size_t)(m0 + lrow) * HH + lc * 8;
    const __nv_bfloat16* Ag1 = Ag0 + (size_t)64 * HH;
    const __nv_bfloat16* Bg0 = Wbf + (size_t)(n0 + lrow) * HH + lc * 8;
    const __nv_bfloat16* Bg1 = Bg0 + (size_t)64 * HH;
    __nv_bfloat16* sA0 = sA + lrow * SPAD + lc * 8;
    __nv_bfloat16* sA1 = sA0 + 64 * SPAD;
    __nv_bfloat16* sB0 = sB + lrow * SPAD + lc * 8;
    __nv_bfloat16* sB1 = sB0 + 64 * SPAD;

    uint4 ra0 = *(const uint4*)Ag0;
    uint4 ra1 = *(const uint4*)Ag1;
    uint4 rb0 = *(const uint4*)Bg0;
    uint4 rb1 = *(const uint4*)Bg1;

    // compute-side bases
    const int mw = (wid >> 2) * 64, nw = (wid & 3) * 32;
    const int qr = lane >> 2, qc = lane & 3;
    const __nv_bfloat16* pa = sA + (mw + qr) * SPAD + qc * 2;
    const __nv_bfloat16* pb = sB + (nw + qr) * SPAD + qc * 2;

    float acc[4][4][4];
    #pragma unroll
    for (int i = 0; i < 4; i++)
        #pragma unroll
        for (int j = 0; j < 4; j++)
            #pragma unroll
            for (int e = 0; e < 4; e++) acc[i][j][e] = 0.f;

    #pragma unroll 1
    for (int kt = 0; kt < 16; kt++) {
        *(uint4*)sA0 = ra0; *(uint4*)sA1 = ra1;
        *(uint4*)sB0 = rb0; *(uint4*)sB1 = rb1;
        __syncthreads();
        if (kt < 15) {
            ra0 = *(const uint4*)(Ag0 + (kt + 1) * 32);
            ra1 = *(const uint4*)(Ag1 + (kt + 1) * 32);
            rb0 = *(const uint4*)(Bg0 + (kt + 1) * 32);
            rb1 = *(const uint4*)(Bg1 + (kt + 1) * 32);
        }
        #pragma unroll
        for (int ks = 0; ks < 2; ks++) {
            uint32_t af[4][4], bf[4][2];
            #pragma unroll
            for (int mi = 0; mi < 4; mi++) {
                const __nv_bfloat16* p = pa + mi * 16 * SPAD + ks * 16;
                af[mi][0] = *(const uint32_t*)(p);
                af[mi][1] = *(const uint32_t*)(p + 8 * SPAD);
                af[mi][2] = *(const uint32_t*)(p + 8);
                af[mi][3] = *(const uint32_t*)(p + 8 * SPAD + 8);
            }
            #pragma unroll
            for (int ni = 0; ni < 4; ni++) {
                const __nv_bfloat16* p = pb + ni * 8 * SPAD + ks * 16;
                bf[ni][0] = *(const uint32_t*)(p);
                bf[ni][1] = *(const uint32_t*)(p + 8);
            }
            #pragma unroll
            for (int mi = 0; mi < 4; mi++)
                #pragma unroll
                for (int ni = 0; ni < 4; ni++)
                    mma16816(acc[mi][ni], af[mi], bf[ni]);
        }
        __syncthreads();
    }

    // epilogue: bias + store (permuted rows) + exp row-partials
    float es[8];
    #pragma unroll
    for (int i = 0; i < 8; i++) es[i] = 0.f;

    #pragma unroll
    for (int mi = 0; mi < 4; mi++) {
        const int rA = m0 + mw + mi * 16 + qr;        // global m of c0,c1
        const int rB = rA + 8;                        // global m of c2,c3
        const int tqA = rA >> 5, bqA = rA & 31;
        const int tqB = rB >> 5, bqB = rB & 31;
        float* cpA = logp + (size_t)(bqA * TT + tqA) * VV + n0;
        float* cpB = logp + (size_t)(bqB * TT + tqB) * VV + n0;
        #pragma unroll
        for (int ni = 0; ni < 4; ni++) {
            const int cl = nw + ni * 8 + qc * 2;      // local col in [0,128)
            float v0 = acc[mi][ni][0] + sbias[cl];
            float v1 = acc[mi][ni][1] + sbias[cl + 1];
            float v2 = acc[mi][ni][2] + sbias[cl];
            float v3 = acc[mi][ni][3] + sbias[cl + 1];
            *(float2*)(cpA + cl) = make_float2(v0, v1);
            *(float2*)(cpB + cl) = make_float2(v2, v3);
            es[mi * 2 + 0] += __expf(v0) + __expf(v1);
            es[mi * 2 + 1] += __expf(v2) + __expf(v3);
        }
    }
    // quad reduce (lanes sharing qr): xor over the two low lane bits
    #pragma unroll
    for (int i = 0; i < 8; i++) {
        es[i] += __shfl_xor_sync(0xffffffffu, es[i], 1);
        es[i] += __shfl_xor_sync(0xffffffffu, es[i], 2);
    }
    if (qc == 0) {
        const int col = blockIdx.y * 4 + (wid & 3);
        #pragma unroll
        for (int mi = 0; mi < 4; mi++) {
            int rA = m0 + mw + mi * 16 + qr;
            int rB = rA + 8;
            int rowA = (rA & 31) * TT + (rA >> 5);
            int rowB = (rB & 31) * TT + (rB >> 5);
            psum[(size_t)rowA * 1024 + col] = es[mi * 2 + 0];
            psum[(size_t)rowB * 1024 + col] = es[mi * 2 + 1];
        }
    }
}

// ---------------- fp32 big GEMM (e2u / gxe), register double-buffered -------------
__global__ __launch_bounds__(256, 2)
void big128_kernel(const float* __restrict__ A, int lda,
                   const int* __restrict__ tokens,
                   const float* __restrict__ W, int ldw,
                   const float* __restrict__ bias, int K,
                   float* __restrict__ C, int ldc, int mode)
{
    __shared__ __align__(16) float sA[16][132];
    __shared__ __align__(16) float sB[16][132];
    const int tid = threadIdx.x;
    const int m0 = blockIdx.x * 128;
    const int n0 = blockIdx.y * 128;
    const int tx4 = (tid & 15) * 4;
    const int ty4 = (tid >> 4) * 4;

    const int row0 = tid >> 2,         kq0 = (tid & 3) * 4;
    const int row1 = (tid + 256) >> 2;
    long ar0 = tokens ? (long)tokens[m0 + row0] : (long)(m0 + row0);
    long ar1 = tokens ? (long)tokens[m0 + row1] : (long)(m0 + row1);
    const float* ap0 = A + ar0 * lda + kq0;
    const float* ap1 = A + ar1 * lda + kq0;
    const float* wp0 = W + (size_t)(n0 + row0) * ldw + kq0;
    const float* wp1 = W + (size_t)(n0 + row1) * ldw + kq0;

    float4 ra0 = *(const float4*)ap0;
    float4 ra1 = *(const float4*)ap1;
    float4 rw0 = *(const float4*)wp0;
    float4 rw1 = *(const float4*)wp1;

    ull acc[4][8];
    #pragma unroll
    for (int i = 0; i < 4; i++)
        #pragma unroll
        for (int j = 0; j < 8; j++) acc[i][j] = 0ull;

    const int kTiles = K / 16;
    for (int kt = 0; kt < kTiles; kt++) {
        sA[kq0 + 0][row0] = ra0.x; sA[kq0 + 1][row0] = ra0.y;
        sA[kq0 + 2][row0] = ra0.z; sA[kq0 + 3][row0] = ra0.w;
        sA[kq0 + 0][row1] = ra1.x; sA[kq0 + 1][row1] = ra1.y;
        sA[kq0 + 2][row1] = ra1.z; sA[kq0 + 3][row1] = ra1.w;
        sB[kq0 + 0][row0] = rw0.x; sB[kq0 + 1][row0] = rw0.y;
        sB[kq0 + 2][row0] = rw0.z; sB[kq0 + 3][row0] = rw0.w;
        sB[kq0 + 0][row1] = rw1.x; sB[kq0 + 1][row1] = rw1.y;
        sB[kq0 + 2][row1] = rw1.z; sB[kq0 + 3][row1] = rw1.w;
        __syncthreads();
        if (kt + 1 < kTiles) {
            int ko = (kt + 1) * 16;
            ra0 = *(const float4*)(ap0 + ko);
            ra1 = *(const float4*)(ap1 + ko);
            rw0 = *(const float4*)(wp0 + ko);
            rw1 = *(const float4*)(wp1 + ko);
        }
        #pragma unroll
        for (int k = 0; k < 16; k++) {
            ulonglong2 a0 = *(const ulonglong2*)&sA[k][ty4];
            ulonglong2 a1 = *(const ulonglong2*)&sA[k][64 + ty4];
            float4 b0 = *(const float4*)&sB[k][tx4];
            float4 b1 = *(const float4*)&sB[k][64 + tx4];
            ull ap[4] = {a0.x, a0.y, a1.x, a1.y};
            ull bd[8] = {dup2(b0.x), dup2(b0.y), dup2(b0.z), dup2(b0.w),
                         dup2(b1.x), dup2(b1.y), dup2(b1.z), dup2(b1.w)};
            #pragma unroll
            for (int mp = 0; mp < 4; mp++)
                #pragma unroll
                for (int n = 0; n < 8; n++)
                    ffma2(acc[mp][n], ap[mp], bd[n]);
        }
        __syncthreads();
    }

    float4 bs0 = *(const float4*)&bias[n0 + tx4];
    float4 bs1 = *(const float4*)&bias[n0 + 64 + tx4];
    #pragma unroll
    for (int mp = 0; mp < 4; mp++) {
        #pragma unroll
        for (int half = 0; half < 2; half++) {
            int gm = m0 + (mp >> 1) * 64 + ty4 + (mp & 1) * 2 + half;
            float v[8];
            #pragma unroll
            for (int n = 0; n < 8; n++) {
                float2 p = unpack2(acc[mp][n]);
                v[n] = half ? p.y : p.x;
            }
            v[0] += bs0.x; v[1] += bs0.y; v[2] += bs0.z; v[3] += bs0.w;
            v[4] += bs1.x; v[5] += bs1.y; v[6] += bs1.z; v[7] += bs1.w;
            if (mode == 2) {
                #pragma unroll
                for (int n = 0; n < 8; n++) v[n] = __expf(2.f * v[n]);
            }
            float* cp = C + (size_t)gm * ldc + n0;
            *(float4*)(cp + tx4)      = make_float4(v[0], v[1], v[2], v[3]);
            *(float4*)(cp + 64 + tx4) = make_float4(v[4], v[5], v[6], v[7]);
        }
    }
}

// ---------------- small gemm (h0 only) --------------------------------------------
__global__ void gemm_tn_kernel(const float* __restrict__ A, int lda,
                               const float* __restrict__ W, int ldb,
                               float* __restrict__ C, int ldc,
                               const float* __restrict__ bias, int K)
{
    __shared__ float sa[TILE_K][33];
    __shared__ float sb[TILE_K][132];
    const int tid = threadIdx.x;
    const int n0 = blockIdx.x * 128;
    const int vq = tid & 31, bg = tid >> 5;
    const int lm = tid >> 3, lk = (tid & 7) * 4;
    float acc[4][4] = {};
    for (int k0 = 0; k0 < K; k0 += TILE_K) {
        float4 a4 = *(const float4*)(A + (size_t)lm * lda + k0 + lk);
        sa[lk + 0][lm] = a4.x; sa[lk + 1][lm] = a4.y;
        sa[lk + 2][lm] = a4.z; sa[lk + 3][lm] = a4.w;
        #pragma unroll
        for (int it = 0; it < 4; it++) {
            int n = lm + 32 * it;
            float4 b4 = *(const float4*)(W + (size_t)(n0 + n) * ldb + k0 + lk);
            sb[lk + 0][n] = b4.x; sb[lk + 1][n] = b4.y;
            sb[lk + 2][n] = b4.z; sb[lk + 3][n] = b4.w;
        }
        __syncthreads();
        #pragma unroll 8
        for (int k = 0; k < TILE_K; k++) {
            float4 bv = *(const float4*)(&sb[k][vq * 4]);
            float a0 = sa[k][bg * 4 + 0], a1 = sa[k][bg * 4 + 1];
            float a2 = sa[k][bg * 4 + 2], a3 = sa[k][bg * 4 + 3];
            acc[0][0] += bv.x * a0; acc[0][1] += bv.x * a1; acc[0][2] += bv.x * a2; acc[0][3] += bv.x * a3;
            acc[1][0] += bv.y * a0; acc[1][1] += bv.y * a1; acc[1][2] += bv.y * a2; acc[1][3] += bv.y * a3;
            acc[2][0] += bv.z * a0; acc[2][1] += bv.z * a1; acc[2][2] += bv.z * a2; acc[2][3] += bv.z * a3;
            acc[3][0] += bv.w * a0; acc[3][1] += bv.w * a1; acc[3][2] += bv.w * a2; acc[3][3] += bv.w * a3;
        }
        __syncthreads();
    }
    float4 bs4 = *(const float4*)(bias + n0 + vq * 4);
    #pragma unroll
    for (int j = 0; j < 4; j++) {
        float4 o;
        o.x = acc[0][j] + bs4.x; o.y = acc[1][j] + bs4.y;
        o.z = acc[2][j] + bs4.z; o.w = acc[3][j] + bs4.w;
        *(float4*)(C + (size_t)(bg * 4 + j) * ldc + n0 + vq * 4) = o;
    }
}

// ---------------- split-K partial GEMM (loop GRU) ----------------------------------
__global__ void pgemm_kernel(const float* __restrict__ A1, int lda1,
                             const float* __restrict__ W1, int ldw1,
                             const float* __restrict__ A2, int lda2,
                             const float* __restrict__ W2, int ldw2,
                             int slices1, int kPerSlice,
                             float* __restrict__ out, int ldo, int sliceStride)
{
    __shared__ float sxh[TILE_K][33];
    __shared__ float sw[TILE_K][68];
    const int tid = threadIdx.x;
    const int s = blockIdx.y;
    const int n0 = blockIdx.x * 64;
    const float* a; int la; const float* w; int lw;
    if (s < slices1) { a = A1 + s * kPerSlice; la = lda1; w = W1 + s * kPerSlice; lw = ldw1; }
    else { a = A2; la = lda2; w = W2; lw = ldw2; }
    const int kTiles = kPerSlice / TILE_K;
    const int lb = tid >> 2, lk = (tid & 3) * 4;
    const int ln = tid >> 3, lk8 = (tid & 7) * 4;
    const int vq = tid & 15, bg = tid >> 4;

    float4 ra[2], rw[4];
    #pragma unroll
    for (int it = 0; it < 2; it++)
        ra[it] = *(const float4*)(a + (size_t)lb * la + lk + 16 * it);
    #pragma unroll
    for (int it = 0; it < 4; it++)
        rw[it] = *(const float4*)(w + (size_t)(n0 + ln + 16 * it) * lw + lk8);

    float acc[4][4] = {};
    for (int kt = 0; kt < kTiles; kt++) {
        #pragma unroll
        for (int it = 0; it < 2; it++) {
            int kk = lk + 16 * it;
            sxh[kk + 0][lb] = ra[it].x; sxh[kk + 1][lb] = ra[it].y;
            sxh[kk + 2][lb] = ra[it].z; sxh[kk + 3][lb] = ra[it].w;
        }
        #pragma unroll
        for (int it = 0; it < 4; it++) {
            int n = ln + 16 * it;
            sw[lk8 + 0][n] = rw[it].x; sw[lk8 + 1][n] = rw[it].y;
            sw[lk8 + 2][n] = rw[it].z; sw[lk8 + 3][n] = rw[it].w;
        }
        __syncthreads();
        if (kt + 1 < kTiles) {
            int ko = (kt + 1) * TILE_K;
            #pragma unroll
            for (int it = 0; it < 2; it++)
                ra[it] = *(const float4*)(a + (size_t)lb * la + ko + lk + 16 * it);
            #pragma unroll
            for (int it = 0; it < 4; it++)
                rw[it] = *(const float4*)(w + (size_t)(n0 + ln + 16 * it) * lw + ko + lk8);
        }
        #pragma unroll 8
        for (int k = 0; k < TILE_K; k++) {
            float4 wv = *(const float4*)(&sw[k][vq * 4]);
            float a0 = sxh[k][bg * 4 + 0], a1 = sxh[k][bg * 4 + 1];
            float a2 = sxh[k][bg * 4 + 2], a3 = sxh[k][bg * 4 + 3];
            acc[0][0] += wv.x * a0; acc[0][1] += wv.x * a1; acc[0][2] += wv.x * a2; acc[0][3] += wv.x * a3;
            acc[1][0] += wv.y * a0; acc[1][1] += wv.y * a1; acc[1][2] += wv.y * a2; acc[1][3] += wv.y * a3;
            acc[2][0] += wv.z * a0; acc[2][1] += wv.z * a1; acc[2][2] += wv.z * a2; acc[2][3] += wv.z * a3;
            acc[3][0] += wv.w * a0; acc[3][1] += wv.w * a1; acc[3][2] += wv.w * a2; acc[3][3] += wv.w * a3;
        }
        __syncthreads();
    }
    #pragma unroll
    for (int j = 0; j < 4; j++) {
        int b = bg * 4 + j;
        *(float4*)(out + (size_t)s * sliceStride + (size_t)b * ldo + n0 + vq * 4) =
            make_float4(acc[0][j], acc[1][j], acc[2][j], acc[3][j]);
    }
}

// ---------------- fused per-step attention (+ previous step's gates) --------------
__global__ void attn_step_kernel(const float* __restrict__ Wa_w,
                                 const float* __restrict__ Wa_b,
                                 const float* __restrict__ Va_w,
                                 const float* __restrict__ Va_b,
                                 const float* __restrict__ enc,
                                 const float* __restrict__ b_hh,
                                 float* __restrict__ attn_out, int t)
{
    __shared__ __align__(16) float sh_h[HH];
    __shared__ __align__(16) float se[HH];
    __shared__ __align__(16) float sva[HH];
    __shared__ float ssc[SS];
    __shared__ float sms[2];
    const int b = blockIdx.x;
    const int tid = threadIdx.x;
    const int warp = tid >> 5, lane = tid & 31;

    if (t > 0) {
        const int j = tid;
        const float* p0 = g_part + (size_t)(0 * BB + b) * (3 * HH);
        const float* p1 = g_part + (size_t)(1 * BB + b) * (3 * HH);
        const float* p2 = g_part + (size_t)(2 * BB + b) * (3 * HH);
        const float* ge = g_gxe + ((size_t)(t - 1) * BB + b) * (3 * HH);
        float gx_r = ge[j] + p0[j] + p1[j];
        float gh_r = p2[j] + b_hh[j];
        float gx_z = ge[j + HH] + p0[j + HH] + p1[j + HH];
        float gh_z = p2[j + HH] + b_hh[j + HH];
        float gx_n = ge[j + 2 * HH] + p0[j + 2 * HH] + p1[j + 2 * HH];
        float gh_n = p2[j + 2 * HH] + b_hh[j + 2 * HH];
        float r = sig_f(gx_r + gh_r);
        float z = sig_f(gx_z + gh_z);
        float n = tanh_f(gx_n + r * gh_n);
        float hp = g_Hall[(size_t)(t - 1) * BB * HH + b * HH + j];
        float hn = (1.f - z) * n + z * hp;
        sh_h[j] = hn;
        g_Hall[(size_t)t * BB * HH + b * HH + j] = hn;
    } else {
        sh_h[tid] = g_Hall[b * HH + tid];
    }
    sva[tid] = Va_w[tid];
    __syncthreads();

    const float4* sh4 = (const float4*)sh_h;
    for (int rr = 0; rr < 32; rr++) {
        int i = warp * 32 + rr;
        const float4* wrow = (const float4*)(Wa_w + (size_t)i * HH);
        float sum = 0.f;
        #pragma unroll
        for (int it = 0; it < 4; it++) {
            int idx = lane + 32 * it;
            float4 w4 = wrow[idx];
            float4 h4 = sh4[idx];
            sum += w4.x * h4.x + w4.y * h4.y + w4.z * h4.z + w4.w * h4.w;
        }
        #pragma unroll
        for (int o = 16; o; o >>= 1) sum += __shfl_xor_sync(~0u, sum, o);
        if (lane == 0) se[i] = __expf(2.f * (sum + Wa_b[i]));
    }
    __syncthreads();

    const float4* se4 = (const float4*)se;
    const float4* sva4 = (const float4*)sva;
    for (int ss = 0; ss < 4; ss++) {
        int s = warp * 4 + ss;
        const float4* eu = (const float4*)(g_eu + (size_t)(b * SS + s) * HH);
        float sum = 0.f;
        #pragma unroll
        for (int it = 0; it < 4; it++) {
            int idx = lane + 32 * it;
            float4 e4 = eu[idx];
            float4 q4 = se4[idx];
            float4 v4 = sva4[idx];
            sum += v4.x * (1.f - 2.f * rcpf(q4.x * e4.x + 1.f));
            sum += v4.y * (1.f - 2.f * rcpf(q4.y * e4.y + 1.f));
            sum += v4.z * (1.f - 2.f * rcpf(q4.z * e4.z + 1.f));
            sum += v4.w * (1.f - 2.f * rcpf(q4.w * e4.w + 1.f));
        }
        #pragma unroll
        for (int o = 16; o; o >>= 1) sum += __shfl_xor_sync(~0u, sum, o);
        if (lane == 0) ssc[s] = sum + Va_b[0];
    }
    __syncthreads();

    if (tid == 0) {
        float m = ssc[0];
        for (int s = 1; s < SS; s++) m = fmaxf(m, ssc[s]);
        float sm = 0.f;
        for (int s = 0; s < SS; s++) sm += __expf(ssc[s] - m);
        sms[0] = m; sms[1] = rcpf(sm);
    }
    __syncthreads();
    if (tid < SS) {
        float w = __expf(ssc[tid] - sms[0]) * sms[1];
        ssc[tid] = w;
        attn_out[((size_t)b * TT + t) * SS + tid] = w;
    }
    __syncthreads();

    for (int kk = tid; kk < 2 * HH; kk += 512) {
        float a = 0.f;
        #pragma unroll 8
        for (int s = 0; s < SS; s++)
            a += ssc[s] * enc[(size_t)(b * SS + s) * (2 * HH) + kk];
        g_ctx[b * 2 * HH + kk] = a;
    }
}

__global__ void gates_kernel(const float* __restrict__ gxe_t,
                             const float* __restrict__ b_hh,
                             const float* __restrict__ h_old,
                             float* __restrict__ h_new,
                             float* __restrict__ h_new2)
{
    const int b = blockIdx.x;
    const int j = threadIdx.x;
    const float* p0 = g_part + (size_t)(0 * BB + b) * (3 * HH);
    const float* p1 = g_part + (size_t)(1 * BB + b) * (3 * HH);
    const float* p2 = g_part + (size_t)(2 * BB + b) * (3 * HH);
    const float* ge = gxe_t + (size_t)b * (3 * HH);
    float gx_r = ge[j] + p0[j] + p1[j];
    float gh_r = p2[j] + b_hh[j];
    float gx_z = ge[j + HH] + p0[j + HH] + p1[j + HH];
    float gh_z = p2[j + HH] + b_hh[j + HH];
    float gx_n = ge[j + 2 * HH] + p0[j + 2 * HH] + p1[j + 2 * HH];
    float gh_n = p2[j + 2 * HH] + b_hh[j + 2 * HH];
    float r = sig_f(gx_r + gh_r);
    float z = sig_f(gx_z + gh_z);
    float n = tanh_f(gx_n + r * gh_n);
    float hv = (1.f - z) * n + z * h_old[b * HH + j];
    h_new[b * HH + j] = hv;
    h_new2[b * HH + j] = hv;
}

__global__ void lsm_final_kernel(float* __restrict__ logp)
{
    const int r = blockIdx.x;
    __shared__ float sred[8];
    __shared__ float sls;
    const int tid = threadIdx.x;  // 256
    float s = 0.f;
    for (int i = tid; i < 1000; i += 256)
        s += g_psum[(size_t)r * 1024 + i];
    #pragma unroll
    for (int o = 16; o; o >>= 1) s += __shfl_down_sync(~0u, s, o);
    if ((tid & 31) == 0) sred[tid >> 5] = s;
    __syncthreads();
    if (tid == 0) {
        float tot = 0.f;
        for (int w = 0; w < 8; w++) tot += sred[w];
        sls = logf(tot);
    }
    __syncthreads();
    float ls = sls;
    float* row = logp + (size_t)r * VV;
    for (int i = tid * 4; i < VV; i += 1024) {
        float4 v = *(float4*)(row + i);
        v.x -= ls; v.y -= ls; v.z -= ls; v.w -= ls;
        *(float4*)(row + i) = v;
    }
}

// ---------------- launcher ---------------------------------------------------------
extern "C" void kernel_launch(void* const* d_in, const int* in_sizes, int n_in,
                              void* d_out, int out_size)
{
    const float* enc   = (const float*)d_in[0];
    const float* ehid  = (const float*)d_in[1];
    const int*   tgt   = (const int*)  d_in[2];
    const float* emb   = (const float*)d_in[3];
    const float* Wa_w  = (const float*)d_in[4];
    const float* Wa_b  = (const float*)d_in[5];
    const float* Ua_w  = (const float*)d_in[6];
    const float* Ua_b  = (const float*)d_in[7];
    const float* Va_w  = (const float*)d_in[8];
    const float* Va_b  = (const float*)d_in[9];
    const float* W_ih  = (const float*)d_in[10];
    const float* b_ih  = (const float*)d_in[11];
    const float* W_hh  = (const float*)d_in[12];
    const float* b_hh  = (const float*)d_in[13];
    const float* Wh    = (const float*)d_in[14];
    const float* bh    = (const float*)d_in[15];
    const float* out_w = (const float*)d_in[16];
    const float* out_b = (const float*)d_in[17];

    float* outp = (float*)d_out;
    float* logp = outp;
    float* hfin = outp + (size_t)BB * TT * VV;
    float* attn = hfin + (size_t)BB * HH;

    float *hall, *eu, *gxe, *ctx, *part, *psum;
    int* tokp;
    __nv_bfloat16 *hbf, *wbf;
    cudaGetSymbolAddress((void**)&hall, g_Hall);
    cudaGetSymbolAddress((void**)&eu,   g_eu);
    cudaGetSymbolAddress((void**)&gxe,  g_gxe);
    cudaGetSymbolAddress((void**)&ctx,  g_ctx);
    cudaGetSymbolAddress((void**)&part, g_part);
    cudaGetSymbolAddress((void**)&psum, g_psum);
    cudaGetSymbolAddress((void**)&tokp, g_tok);
    cudaGetSymbolAddress((void**)&hbf,  g_Hbf);
    cudaGetSymbolAddress((void**)&wbf,  g_Wbf);

    tok_kernel<<<4, 256>>>(tgt);
    gemm_tn_kernel<<<dim3(4, 1), 256>>>(ehid, 2 * HH, Wh, 2 * HH, hall, HH, bh, 2 * HH);
    big128_kernel<<<dim3(16, 4), 256>>>(enc, 2 * HH, nullptr, Ua_w, 2 * HH, Ua_b,
                                        2 * HH, eu, HH, 2);
    big128_kernel<<<dim3(8, 12), 256>>>(emb, HH, tokp, W_ih, 3 * HH, b_ih,
                                        HH, gxe, 3 * HH, 1);
    conv_bf16_kernel<<<4000, 256>>>(out_w, wbf, VV * HH / 4);

    for (int t = 0; t < TT; t++) {
        float* hcur = hall + (size_t)t * BB * HH;
        attn_step_kernel<<<BB, 512>>>(Wa_w, Wa_b, Va_w, Va_b, enc, b_hh, attn, t);
        pgemm_kernel<<<dim3(24, 3), 128>>>(ctx, 2 * HH, W_ih + HH, 3 * HH,
                                           hcur, HH, W_hh, HH,
                                           2, HH, part, 3 * HH, BB * 3 * HH);
    }
    gates_kernel<<<BB, 512>>>(gxe + (size_t)31 * BB * 3 * HH, b_hh,
                              hall + (size_t)31 * BB * HH,
                              hall + (size_t)32 * BB * HH, hfin);

    conv_bf16_kernel<<<512, 256>>>(hall + BB * HH, hbf, TT * BB * HH / 4);
    logits_hmma_kernel<<<dim3(8, 250), 256>>>(hbf, wbf, out_b, logp, psum);
    lsm_final_kernel<<<BB * TT, 256>>>(logp);
}